// round 7
// baseline (speedup 1.0000x reference)
#include <cuda_runtime.h>
#include <math.h>
#include <stdint.h>

#define B_  2
#define S_  2048
#define D_  1024
#define H_  16
#define HD_ 64
#define M_  (B_ * S_)    // 4096
#define N3_ (3 * D_)     // 3072

// Scratch for Q/K/V in (b*H+h, s, e) layout.
__device__ float g_Q[(size_t)M_ * D_];
__device__ float g_K[(size_t)M_ * D_];
__device__ float g_V[(size_t)M_ * D_];

// ---------------------------------------------------------------------------
// TF32 helpers
// ---------------------------------------------------------------------------
__device__ __forceinline__ uint32_t f2tf(float x) {
    uint32_t r;
    asm("cvt.rna.tf32.f32 %0, %1;" : "=r"(r) : "f"(x));
    return r;
}
__device__ __forceinline__ float tf32r(float x) {
    uint32_t r;
    asm("cvt.rna.tf32.f32 %0, %1;" : "=r"(r) : "f"(x));
    return __uint_as_float(r);
}
__device__ __forceinline__ float ex2(float x) {
    float r;
    asm("ex2.approx.f32 %0, %1;" : "=f"(r) : "f"(x));
    return r;
}
__device__ __forceinline__ void mma_tf32(float c[4],
    uint32_t a0, uint32_t a1, uint32_t a2, uint32_t a3,
    uint32_t b0, uint32_t b1)
{
    asm volatile(
        "mma.sync.aligned.m16n8k8.row.col.f32.tf32.tf32.f32 "
        "{%0,%1,%2,%3}, {%4,%5,%6,%7}, {%8,%9}, {%0,%1,%2,%3};"
        : "+f"(c[0]), "+f"(c[1]), "+f"(c[2]), "+f"(c[3])
        : "r"(a0), "r"(a1), "r"(a2), "r"(a3), "r"(b0), "r"(b1));
}

// Q scale: 1/sqrt(64) * log2(e)  -> scores land in log2 domain, softmax via ex2
#define QSCALE 0.1803368801111204f

// ---------------------------------------------------------------------------
// Kernel 1: QKV projection, split-TF32 MMA, double-buffered smem stages,
// interleaved (hi,lo) float2 storage (1 LDS.64 per fragment pair).
// BM=128, BN=128, BK=16, 256 threads, warps 4(M)x2(N), warp tile 32x64.
// A: 128 rows x 16 float2, pitch 20 (20 mod 16 = 4 -> 4g+t conflict-free).
// W: 16 rows x 128 float2, pitch 132 (132 mod 16 = 4 -> 4t+g conflict-free).
// ---------------------------------------------------------------------------
#define AP2 20
#define WP2 132
#define A2SZ (128 * AP2)     // float2 per A buffer = 2560
#define W2SZ (16 * WP2)      // float2 per W buffer = 2112
#define QKV_SMEM_BYTES ((A2SZ + W2SZ) * 2 * (int)sizeof(float2))  // 74752

__global__ __launch_bounds__(256, 2) void qkv_mma_kernel(
    const float* __restrict__ A, const float* __restrict__ W,
    const float* __restrict__ qbias, const float* __restrict__ vbias)
{
    extern __shared__ float2 sm2[];
    float2* Ab[2] = { sm2, sm2 + A2SZ };
    float2* Wb[2] = { sm2 + 2 * A2SZ, sm2 + 2 * A2SZ + W2SZ };

    const int tid  = threadIdx.x;
    const int warp = tid >> 5;
    const int lane = tid & 31;
    const int g    = lane >> 2;
    const int t    = lane & 3;
    const int bm   = blockIdx.y * 128;
    const int bn   = blockIdx.x * 128;
    const int warpM = (warp >> 1) * 32;
    const int warpN = (warp & 1) * 64;

    float C[2][8][4];
    #pragma unroll
    for (int mf = 0; mf < 2; mf++)
        #pragma unroll
        for (int nf = 0; nf < 8; nf++)
            #pragma unroll
            for (int j = 0; j < 4; j++) C[mf][nf][j] = 0.f;

    // staging coords: 2 float4 for A, 2 float4 for W per thread per slab
    int arow[2], acg[2], wkk[2], wnn[2];
    float4 pa[2], pw[2];
    #pragma unroll
    for (int i = 0; i < 2; i++) {
        int idx = tid + i * 256;
        arow[i] = idx >> 2;
        acg[i]  = (idx & 3) << 2;
        wkk[i]  = idx >> 5;
        wnn[i]  = (idx & 31) << 2;
    }

    // convert regs -> buffer b
    auto stage = [&](int b) {
        #pragma unroll
        for (int i = 0; i < 2; i++) {
            float4 x = pa[i];
            float4 hi = make_float4(tf32r(x.x), tf32r(x.y), tf32r(x.z), tf32r(x.w));
            float2* dst = Ab[b] + arow[i] * AP2 + acg[i];
            *(float4*)dst       = make_float4(hi.x, tf32r(x.x - hi.x), hi.y, tf32r(x.y - hi.y));
            *(float4*)(dst + 2) = make_float4(hi.z, tf32r(x.z - hi.z), hi.w, tf32r(x.w - hi.w));

            float4 y = pw[i];
            float4 whi = make_float4(tf32r(y.x), tf32r(y.y), tf32r(y.z), tf32r(y.w));
            float2* wdst = Wb[b] + wkk[i] * WP2 + wnn[i];
            *(float4*)wdst       = make_float4(whi.x, tf32r(y.x - whi.x), whi.y, tf32r(y.y - whi.y));
            *(float4*)(wdst + 2) = make_float4(whi.z, tf32r(y.z - whi.z), whi.w, tf32r(y.w - whi.w));
        }
    };
    auto fetch = [&](int k0) {
        #pragma unroll
        for (int i = 0; i < 2; i++) {
            pa[i] = *(const float4*)(A + (size_t)(bm + arow[i]) * D_ + k0 * 16 + acg[i]);
            pw[i] = *(const float4*)(W + (size_t)(k0 * 16 + wkk[i]) * N3_ + bn + wnn[i]);
        }
    };

    const int NS = D_ / 16;   // 64 slabs
    fetch(0);
    stage(0);
    fetch(1);
    __syncthreads();

    for (int k0 = 0; k0 < NS; k0++) {
        int cur = k0 & 1;
        if (k0 + 1 < NS) stage(cur ^ 1);
        if (k0 + 2 < NS) fetch(k0 + 2);

        #pragma unroll
        for (int kc = 0; kc < 2; kc++) {
            uint32_t ah[2][4], al[2][4];
            #pragma unroll
            for (int mf = 0; mf < 2; mf++) {
                int r2 = (warpM + mf * 16 + g) * AP2 + kc * 8 + t;
                float2 a0 = Ab[cur][r2];
                float2 a1 = Ab[cur][r2 + 8 * AP2];
                float2 a2 = Ab[cur][r2 + 4];
                float2 a3 = Ab[cur][r2 + 8 * AP2 + 4];
                ah[mf][0] = __float_as_uint(a0.x); al[mf][0] = __float_as_uint(a0.y);
                ah[mf][1] = __float_as_uint(a1.x); al[mf][1] = __float_as_uint(a1.y);
                ah[mf][2] = __float_as_uint(a2.x); al[mf][2] = __float_as_uint(a2.y);
                ah[mf][3] = __float_as_uint(a3.x); al[mf][3] = __float_as_uint(a3.y);
            }
            #pragma unroll
            for (int nf = 0; nf < 8; nf++) {
                int n   = warpN + nf * 8 + g;
                int kb2 = (kc * 8 + t) * WP2 + n;
                float2 b0 = Wb[cur][kb2];
                float2 b1 = Wb[cur][kb2 + 4 * WP2];
                uint32_t bh0 = __float_as_uint(b0.x), bl0 = __float_as_uint(b0.y);
                uint32_t bh1 = __float_as_uint(b1.x), bl1 = __float_as_uint(b1.y);
                #pragma unroll
                for (int mf = 0; mf < 2; mf++) {
                    mma_tf32(C[mf][nf], ah[mf][0], ah[mf][1], ah[mf][2], ah[mf][3], bh0, bh1);
                    mma_tf32(C[mf][nf], ah[mf][0], ah[mf][1], ah[mf][2], ah[mf][3], bl0, bl1);
                    mma_tf32(C[mf][nf], al[mf][0], al[mf][1], al[mf][2], al[mf][3], bh0, bh1);
                }
            }
        }
        __syncthreads();
    }

    const int which = bn >> 10;
    #pragma unroll
    for (int mf = 0; mf < 2; mf++) {
        int mrow = bm + warpM + mf * 16 + g;
        int b = mrow >> 11;
        int s = mrow & (S_ - 1);
        #pragma unroll
        for (int nf = 0; nf < 8; nf++) {
            int ncol = bn + warpN + nf * 8 + 2 * t;
            int d = ncol & (D_ - 1);
            int h = d >> 6;
            int e = d & 63;
            size_t i0 = ((size_t)(b * H_ + h) * S_ + s) * HD_ + e;
            size_t i1 = i0 + 8 * HD_;
            float c0 = C[mf][nf][0], c1 = C[mf][nf][1];
            float c2 = C[mf][nf][2], c3 = C[mf][nf][3];
            if (which == 0) {
                float b0 = qbias[d], b1 = qbias[d + 1];
                *(float2*)&g_Q[i0] = make_float2((c0 + b0) * QSCALE, (c1 + b1) * QSCALE);
                *(float2*)&g_Q[i1] = make_float2((c2 + b0) * QSCALE, (c3 + b1) * QSCALE);
            } else if (which == 1) {
                *(float2*)&g_K[i0] = make_float2(c0, c1);
                *(float2*)&g_K[i1] = make_float2(c2, c3);
            } else {
                float b0 = vbias[d], b1 = vbias[d + 1];
                *(float2*)&g_V[i0] = make_float2(c0 + b0, c1 + b1);
                *(float2*)&g_V[i1] = make_float2(c2 + b0, c3 + b1);
            }
        }
    }
}

// ---------------------------------------------------------------------------
// Kernel 2: flash attention, TF32 MMA.
// Block = 128 threads (4 warps), warp tile M=32, Br=128, Bc=64.
// K stored interleaved (hi,lo) float2 pitch 68 (1 LDS.64 per pair, c-free).
// V single-pass tf32. Softmax in log2 domain (scores pre-scaled by log2e).
// smem: Qs raw [128][68]; Khl [64][68]x2; Vhi [64][72] = 88 KB -> 2 blk/SM.
// ---------------------------------------------------------------------------
#define QP  68
#define KP2 68          // float2 pitch
#define VP  72
#define SM_Q  (128 * QP)             // floats
#define SM_K2 (64 * KP2)             // float2
#define SM_V  (64 * VP)              // floats
#define ATTN_SMEM_BYTES ((SM_Q + SM_V) * 4 + SM_K2 * 8)   // 88064

__global__ __launch_bounds__(128, 2) void attn5_kernel(float* __restrict__ out)
{
    extern __shared__ float sm[];
    float*  Qs  = sm;                               // [128][QP] raw fp32
    float2* Khl = (float2*)(sm + SM_Q);             // [64][KP2] (hi,lo)
    float*  Vhi = sm + SM_Q + SM_K2 * 2;            // [64][VP]

    const int tid  = threadIdx.x;
    const int warp = tid >> 5;
    const int lane = tid & 31;
    const int g    = lane >> 2;
    const int t    = lane & 3;
    const int wm   = warp * 32;
    const int bh   = blockIdx.y;
    const int qt   = blockIdx.x;

    const float* Qg = g_Q + ((size_t)bh * S_ + qt * 128) * HD_;
    const float* Kg = g_K + (size_t)bh * S_ * HD_;
    const float* Vg = g_V + (size_t)bh * S_ * HD_;

    #pragma unroll
    for (int i = 0; i < 16; i++) {
        int idx = tid + i * 128;
        int row = idx >> 4;
        int col = (idx & 15) << 2;
        *(float4*)&Qs[row * QP + col] = *(const float4*)(Qg + row * HD_ + col);
    }

    float m[2][2], l[2][2];
    #pragma unroll
    for (int mf = 0; mf < 2; mf++) {
        m[mf][0] = -INFINITY; m[mf][1] = -INFINITY;
        l[mf][0] = 0.f;       l[mf][1] = 0.f;
    }
    float O[2][8][4];
    #pragma unroll
    for (int mf = 0; mf < 2; mf++)
        #pragma unroll
        for (int nt = 0; nt < 8; nt++)
            #pragma unroll
            for (int j = 0; j < 4; j++) O[mf][nt][j] = 0.f;

    for (int kt = 0; kt < S_ / 64; kt++) {
        __syncthreads();

        // ---- stage K (interleaved hi/lo) and V (hi) ----
        const float* Kt = Kg + (size_t)kt * 64 * HD_;
        const float* Vt = Vg + (size_t)kt * 64 * HD_;
        #pragma unroll
        for (int i = 0; i < 8; i++) {
            int idx = tid + i * 128;
            int row = idx >> 4;
            int col = (idx & 15) << 2;
            float4 kx = *(const float4*)(Kt + row * HD_ + col);
            float4 vx = *(const float4*)(Vt + row * HD_ + col);
            float4 khi = make_float4(tf32r(kx.x), tf32r(kx.y), tf32r(kx.z), tf32r(kx.w));
            float2* kdst = Khl + row * KP2 + col;
            *(float4*)kdst       = make_float4(khi.x, tf32r(kx.x - khi.x),
                                               khi.y, tf32r(kx.y - khi.y));
            *(float4*)(kdst + 2) = make_float4(khi.z, tf32r(kx.z - khi.z),
                                               khi.w, tf32r(kx.w - khi.w));
            *(float4*)&Vhi[row * VP + col] =
                make_float4(tf32r(vx.x), tf32r(vx.y), tf32r(vx.z), tf32r(vx.w));
        }
        __syncthreads();

        // ---- scores (log2 domain): split-TF32 (3 MMA) ----
        float Sf[2][8][4];
        #pragma unroll
        for (int mf = 0; mf < 2; mf++)
            #pragma unroll
            for (int nt = 0; nt < 8; nt++)
                #pragma unroll
                for (int j = 0; j < 4; j++) Sf[mf][nt][j] = 0.f;

        #pragma unroll
        for (int kc = 0; kc < 8; kc++) {
            uint32_t ah[2][4], al[2][4];
            #pragma unroll
            for (int mf = 0; mf < 2; mf++) {
                int qi = (wm + mf * 16 + g) * QP + kc * 8 + t;
                float a0f = Qs[qi];
                float a1f = Qs[qi + 8 * QP];
                float a2f = Qs[qi + 4];
                float a3f = Qs[qi + 8 * QP + 4];
                ah[mf][0] = f2tf(a0f); ah[mf][1] = f2tf(a1f);
                ah[mf][2] = f2tf(a2f); ah[mf][3] = f2tf(a3f);
                al[mf][0] = f2tf(a0f - __uint_as_float(ah[mf][0]));
                al[mf][1] = f2tf(a1f - __uint_as_float(ah[mf][1]));
                al[mf][2] = f2tf(a2f - __uint_as_float(ah[mf][2]));
                al[mf][3] = f2tf(a3f - __uint_as_float(ah[mf][3]));
            }
            #pragma unroll
            for (int nt = 0; nt < 8; nt++) {
                int kb = (nt * 8 + g) * KP2 + kc * 8 + t;
                float2 k0 = Khl[kb];
                float2 k1 = Khl[kb + 4];
                uint32_t bh0 = __float_as_uint(k0.x), bl0 = __float_as_uint(k0.y);
                uint32_t bh1 = __float_as_uint(k1.x), bl1 = __float_as_uint(k1.y);
                #pragma unroll
                for (int mf = 0; mf < 2; mf++) {
                    mma_tf32(Sf[mf][nt], ah[mf][0], ah[mf][1], ah[mf][2], ah[mf][3], bh0, bh1);
                    mma_tf32(Sf[mf][nt], ah[mf][0], ah[mf][1], ah[mf][2], ah[mf][3], bl0, bl1);
                    mma_tf32(Sf[mf][nt], al[mf][0], al[mf][1], al[mf][2], al[mf][3], bh0, bh1);
                }
            }
        }

        // ---- online softmax (base-2) ----
        #pragma unroll
        for (int mf = 0; mf < 2; mf++) {
            float mx0 = -INFINITY, mx1 = -INFINITY;
            #pragma unroll
            for (int nt = 0; nt < 8; nt++) {
                mx0 = fmaxf(mx0, fmaxf(Sf[mf][nt][0], Sf[mf][nt][1]));
                mx1 = fmaxf(mx1, fmaxf(Sf[mf][nt][2], Sf[mf][nt][3]));
            }
            mx0 = fmaxf(mx0, __shfl_xor_sync(0xffffffffu, mx0, 1));
            mx0 = fmaxf(mx0, __shfl_xor_sync(0xffffffffu, mx0, 2));
            mx1 = fmaxf(mx1, __shfl_xor_sync(0xffffffffu, mx1, 1));
            mx1 = fmaxf(mx1, __shfl_xor_sync(0xffffffffu, mx1, 2));

            float mn0 = fmaxf(m[mf][0], mx0);
            float mn1 = fmaxf(m[mf][1], mx1);
            float alp0 = ex2(m[mf][0] - mn0);
            float alp1 = ex2(m[mf][1] - mn1);

            float ls0 = 0.f, ls1 = 0.f;
            #pragma unroll
            for (int nt = 0; nt < 8; nt++) {
                Sf[mf][nt][0] = ex2(Sf[mf][nt][0] - mn0);
                Sf[mf][nt][1] = ex2(Sf[mf][nt][1] - mn0);
                Sf[mf][nt][2] = ex2(Sf[mf][nt][2] - mn1);
                Sf[mf][nt][3] = ex2(Sf[mf][nt][3] - mn1);
                ls0 += Sf[mf][nt][0] + Sf[mf][nt][1];
                ls1 += Sf[mf][nt][2] + Sf[mf][nt][3];
            }
            ls0 += __shfl_xor_sync(0xffffffffu, ls0, 1);
            ls0 += __shfl_xor_sync(0xffffffffu, ls0, 2);
            ls1 += __shfl_xor_sync(0xffffffffu, ls1, 1);
            ls1 += __shfl_xor_sync(0xffffffffu, ls1, 2);

            l[mf][0] = l[mf][0] * alp0 + ls0;  m[mf][0] = mn0;
            l[mf][1] = l[mf][1] * alp1 + ls1;  m[mf][1] = mn1;

            #pragma unroll
            for (int nt = 0; nt < 8; nt++) {
                O[mf][nt][0] *= alp0;  O[mf][nt][1] *= alp0;
                O[mf][nt][2] *= alp1;  O[mf][nt][3] *= alp1;
            }
        }

        // ---- O += P @ V ----
        const int src0 = (lane & ~3) + (t >> 1);
        const int src2 = src0 + 2;
        const bool odd = (t & 1);

        #pragma unroll
        for (int kc = 0; kc < 8; kc++) {
            uint32_t a[2][4];
            #pragma unroll
            for (int mf = 0; mf < 2; mf++) {
                float e0 = __shfl_sync(0xffffffffu, Sf[mf][kc][0], src0);
                float e1 = __shfl_sync(0xffffffffu, Sf[mf][kc][1], src0);
                float f0 = __shfl_sync(0xffffffffu, Sf[mf][kc][0], src2);
                float f1 = __shfl_sync(0xffffffffu, Sf[mf][kc][1], src2);
                float h0 = __shfl_sync(0xffffffffu, Sf[mf][kc][2], src0);
                float h1 = __shfl_sync(0xffffffffu, Sf[mf][kc][3], src0);
                float i0 = __shfl_sync(0xffffffffu, Sf[mf][kc][2], src2);
                float i1 = __shfl_sync(0xffffffffu, Sf[mf][kc][3], src2);
                a[mf][0] = f2tf(odd ? e1 : e0);
                a[mf][1] = f2tf(odd ? h1 : h0);
                a[mf][2] = f2tf(odd ? f1 : f0);
                a[mf][3] = f2tf(odd ? i1 : i0);
            }
            #pragma unroll
            for (int nt = 0; nt < 8; nt++) {
                int vi = (kc * 8 + t) * VP + nt * 8 + g;
                uint32_t bh0 = __float_as_uint(Vhi[vi]);
                uint32_t bh1 = __float_as_uint(Vhi[vi + 4 * VP]);
                #pragma unroll
                for (int mf = 0; mf < 2; mf++)
                    mma_tf32(O[mf][nt], a[mf][0], a[mf][1], a[mf][2], a[mf][3], bh0, bh1);
            }
        }
    }

    // ---- epilogue ----
    int b = bh >> 4;
    int h = bh & 15;
    #pragma unroll
    for (int mf = 0; mf < 2; mf++) {
        float inv0 = 1.f / l[mf][0];
        float inv1 = 1.f / l[mf][1];
        int srow = qt * 128 + wm + mf * 16 + g;
        size_t base0 = ((size_t)(b * S_ + srow) * H_ + h) * HD_;
        size_t base1 = base0 + (size_t)8 * H_ * HD_;
        #pragma unroll
        for (int nt = 0; nt < 8; nt++) {
            int col = nt * 8 + 2 * t;
            *(float2*)&out[base0 + col] =
                make_float2(O[mf][nt][0] * inv0, O[mf][nt][1] * inv0);
            *(float2*)&out[base1 + col] =
                make_float2(O[mf][nt][2] * inv1, O[mf][nt][3] * inv1);
        }
    }
}

extern "C" void kernel_launch(void* const* d_in, const int* in_sizes, int n_in,
                              void* d_out, int out_size)
{
    const float* hs = (const float*)d_in[0];
    const float* w  = (const float*)d_in[1];
    const float* qb = (const float*)d_in[2];
    const float* vb = (const float*)d_in[3];
    float* out = (float*)d_out;

    cudaFuncSetAttribute(qkv_mma_kernel,
                         cudaFuncAttributeMaxDynamicSharedMemorySize, QKV_SMEM_BYTES);
    dim3 g1(N3_ / 128, M_ / 128);   // 24 x 32
    qkv_mma_kernel<<<g1, 256, QKV_SMEM_BYTES>>>(hs, w, qb, vb);

    cudaFuncSetAttribute(attn5_kernel,
                         cudaFuncAttributeMaxDynamicSharedMemorySize, ATTN_SMEM_BYTES);
    dim3 g2(S_ / 128, B_ * H_);     // 16 x 32
    attn5_kernel<<<g2, 128, ATTN_SMEM_BYTES>>>(out);
}

// round 8
// speedup vs baseline: 1.1296x; 1.1296x over previous
#include <cuda_runtime.h>
#include <math.h>
#include <stdint.h>

#define B_  2
#define S_  2048
#define D_  1024
#define H_  16
#define HD_ 64
#define M_  (B_ * S_)    // 4096
#define N3_ (3 * D_)     // 3072

// Scratch buffers.
__device__ float2 g_A2[(size_t)M_ * D_];    // A pre-split (hi,lo)
__device__ float2 g_W2[(size_t)D_ * N3_];   // W pre-split (hi,lo)
__device__ float g_Q[(size_t)M_ * D_];      // raw fp32, pre-scaled
__device__ float g_K[(size_t)M_ * D_];      // tf32-rounded
__device__ float g_V[(size_t)M_ * D_];      // tf32-rounded

// ---------------------------------------------------------------------------
// TF32 helpers
// ---------------------------------------------------------------------------
__device__ __forceinline__ uint32_t f2tf(float x) {
    uint32_t r;
    asm("cvt.rna.tf32.f32 %0, %1;" : "=r"(r) : "f"(x));
    return r;
}
__device__ __forceinline__ float tf32r(float x) {
    uint32_t r;
    asm("cvt.rna.tf32.f32 %0, %1;" : "=r"(r) : "f"(x));
    return __uint_as_float(r);
}
__device__ __forceinline__ float ex2(float x) {
    float r;
    asm("ex2.approx.f32 %0, %1;" : "=f"(r) : "f"(x));
    return r;
}
__device__ __forceinline__ void mma_tf32(float c[4],
    uint32_t a0, uint32_t a1, uint32_t a2, uint32_t a3,
    uint32_t b0, uint32_t b1)
{
    asm volatile(
        "mma.sync.aligned.m16n8k8.row.col.f32.tf32.tf32.f32 "
        "{%0,%1,%2,%3}, {%4,%5,%6,%7}, {%8,%9}, {%0,%1,%2,%3};"
        : "+f"(c[0]), "+f"(c[1]), "+f"(c[2]), "+f"(c[3])
        : "r"(a0), "r"(a1), "r"(a2), "r"(a3), "r"(b0), "r"(b1));
}

// Q scale: 1/sqrt(64) * log2(e) -> scores in log2 domain, softmax via ex2
#define QSCALE 0.1803368801111204f

// ---------------------------------------------------------------------------
// Kernel 0: prepass — split A and W into (hi,lo) tf32 pairs, once.
// ---------------------------------------------------------------------------
__global__ void preconv_kernel(const float* __restrict__ A,
                               const float* __restrict__ W)
{
    const int A4 = (M_ * D_) / 4;       // 1048576
    const int W4 = (D_ * N3_) / 4;      // 786432
    int stride = gridDim.x * blockDim.x;
    for (int i = blockIdx.x * blockDim.x + threadIdx.x; i < A4 + W4; i += stride) {
        float4 x;
        float4* dst;
        if (i < A4) {
            x = ((const float4*)A)[i];
            dst = (float4*)(g_A2 + (size_t)i * 4);
        } else {
            int j = i - A4;
            x = ((const float4*)W)[j];
            dst = (float4*)(g_W2 + (size_t)j * 4);
        }
        float h0 = tf32r(x.x), h1 = tf32r(x.y), h2 = tf32r(x.z), h3 = tf32r(x.w);
        dst[0] = make_float4(h0, tf32r(x.x - h0), h1, tf32r(x.y - h1));
        dst[1] = make_float4(h2, tf32r(x.z - h2), h3, tf32r(x.w - h3));
    }
}

// ---------------------------------------------------------------------------
// Kernel 1: QKV projection, split-TF32 MMA (3-MMA, exact to ~1e-7).
// Round-4 skeleton (proven 448us) but staging is pure copies of pre-split
// data; fragments loaded as LDS.64 (hi,lo) pairs.
// BM=128, BN=128, BK=16, 256 threads, warps 4(M)x2(N), warp tile 32x64.
// Ab pitch 20 f2 (frag banks 8g+2t c-free); Wb pitch 132 f2 (8t+2g.. c-free).
// ---------------------------------------------------------------------------
#define AP2 20
#define WP2 132

__global__ __launch_bounds__(256, 2) void qkv_mma_kernel(
    const float* __restrict__ qbias, const float* __restrict__ vbias)
{
    __shared__ float2 Ab[128 * AP2];   // 20480 B
    __shared__ float2 Wb[16 * WP2];    // 16896 B

    const int tid  = threadIdx.x;
    const int warp = tid >> 5;
    const int lane = tid & 31;
    const int g    = lane >> 2;
    const int t    = lane & 3;
    const int bm   = blockIdx.y * 128;
    const int bn   = blockIdx.x * 128;
    const int warpM = (warp >> 1) * 32;
    const int warpN = (warp & 1) * 64;

    float C[2][8][4];
    #pragma unroll
    for (int mf = 0; mf < 2; mf++)
        #pragma unroll
        for (int nf = 0; nf < 8; nf++)
            #pragma unroll
            for (int j = 0; j < 4; j++) C[mf][nf][j] = 0.f;

    // staging coords: 4 float4 A + 4 float4 W per thread per slab
    int ar[4], ac[4], wr[4], wc[4];
    float4 fa[4], fw[4];
    #pragma unroll
    for (int i = 0; i < 4; i++) {
        int fidx = tid + i * 256;      // 0..1023
        ar[i] = fidx >> 3;             // 0..127 (8 float4 per A row)
        ac[i] = (fidx & 7) << 1;       // float2 col 0..14
        wr[i] = fidx >> 6;             // 0..15 (64 float4 per W row)
        wc[i] = (fidx & 63) << 1;      // float2 col 0..126
    }

    auto fetch = [&](int k0) {
        #pragma unroll
        for (int i = 0; i < 4; i++) {
            fa[i] = *(const float4*)(g_A2 + (size_t)(bm + ar[i]) * D_ + k0 * 16 + ac[i]);
            fw[i] = *(const float4*)(g_W2 + (size_t)(k0 * 16 + wr[i]) * N3_ + bn + wc[i]);
        }
    };

    fetch(0);
    const int NS = D_ / 16;   // 64 slabs

    for (int k0 = 0; k0 < NS; k0++) {
        __syncthreads();   // previous MMA reads done
        #pragma unroll
        for (int i = 0; i < 4; i++) {
            *(float4*)(Ab + ar[i] * AP2 + ac[i]) = fa[i];
            *(float4*)(Wb + wr[i] * WP2 + wc[i]) = fw[i];
        }
        __syncthreads();

        if (k0 + 1 < NS) fetch(k0 + 1);   // overlaps MMA phase

        #pragma unroll
        for (int kc = 0; kc < 2; kc++) {
            uint32_t ah[2][4], al[2][4];
            #pragma unroll
            for (int mf = 0; mf < 2; mf++) {
                int r2 = (warpM + mf * 16 + g) * AP2 + kc * 8 + t;
                float2 a0 = Ab[r2];
                float2 a1 = Ab[r2 + 8 * AP2];
                float2 a2 = Ab[r2 + 4];
                float2 a3 = Ab[r2 + 8 * AP2 + 4];
                ah[mf][0] = __float_as_uint(a0.x); al[mf][0] = __float_as_uint(a0.y);
                ah[mf][1] = __float_as_uint(a1.x); al[mf][1] = __float_as_uint(a1.y);
                ah[mf][2] = __float_as_uint(a2.x); al[mf][2] = __float_as_uint(a2.y);
                ah[mf][3] = __float_as_uint(a3.x); al[mf][3] = __float_as_uint(a3.y);
            }
            #pragma unroll
            for (int nf = 0; nf < 8; nf++) {
                int n   = warpN + nf * 8 + g;
                int kb2 = (kc * 8 + t) * WP2 + n;
                float2 b0 = Wb[kb2];
                float2 b1 = Wb[kb2 + 4 * WP2];
                uint32_t bh0 = __float_as_uint(b0.x), bl0 = __float_as_uint(b0.y);
                uint32_t bh1 = __float_as_uint(b1.x), bl1 = __float_as_uint(b1.y);
                #pragma unroll
                for (int mf = 0; mf < 2; mf++) {
                    mma_tf32(C[mf][nf], ah[mf][0], ah[mf][1], ah[mf][2], ah[mf][3], bh0, bh1);
                    mma_tf32(C[mf][nf], ah[mf][0], ah[mf][1], ah[mf][2], ah[mf][3], bl0, bl1);
                    mma_tf32(C[mf][nf], al[mf][0], al[mf][1], al[mf][2], al[mf][3], bh0, bh1);
                }
            }
        }
    }

    // Epilogue: scatter into (b*H+h, s, e); Q raw*QSCALE, K/V tf32-rounded.
    const int which = bn >> 10;
    #pragma unroll
    for (int mf = 0; mf < 2; mf++) {
        int mrow = bm + warpM + mf * 16 + g;
        int b = mrow >> 11;
        int s = mrow & (S_ - 1);
        #pragma unroll
        for (int nf = 0; nf < 8; nf++) {
            int ncol = bn + warpN + nf * 8 + 2 * t;
            int d = ncol & (D_ - 1);
            int h = d >> 6;
            int e = d & 63;
            size_t i0 = ((size_t)(b * H_ + h) * S_ + s) * HD_ + e;
            size_t i1 = i0 + 8 * HD_;
            float c0 = C[mf][nf][0], c1 = C[mf][nf][1];
            float c2 = C[mf][nf][2], c3 = C[mf][nf][3];
            if (which == 0) {
                float b0 = qbias[d], b1 = qbias[d + 1];
                *(float2*)&g_Q[i0] = make_float2((c0 + b0) * QSCALE, (c1 + b1) * QSCALE);
                *(float2*)&g_Q[i1] = make_float2((c2 + b0) * QSCALE, (c3 + b1) * QSCALE);
            } else if (which == 1) {
                *(float2*)&g_K[i0] = make_float2(tf32r(c0), tf32r(c1));
                *(float2*)&g_K[i1] = make_float2(tf32r(c2), tf32r(c3));
            } else {
                float b0 = vbias[d], b1 = vbias[d + 1];
                *(float2*)&g_V[i0] = make_float2(tf32r(c0 + b0), tf32r(c1 + b1));
                *(float2*)&g_V[i1] = make_float2(tf32r(c2 + b0), tf32r(c3 + b1));
            }
        }
    }
}

// ---------------------------------------------------------------------------
// Kernel 2: flash attention, TF32 MMA.
// Block = 128 threads (4 warps), warp tile M=32, Br=128, Bc=64.
// QK = 2 MMAs (q_hi*k_hi + q_lo*k_hi); K and V arrive tf32-rounded from qkv,
// staging is pure copies. Softmax in log2 domain via ex2.
// smem: Qs [128][68] raw + Khi [64][68] + Vt [64][72] = 70656 B -> 2 blk/SM.
// ---------------------------------------------------------------------------
#define QP 68
#define KP 68
#define VP 72
#define SM_Q (128 * QP)
#define SM_K (64 * KP)
#define SM_V (64 * VP)
#define ATTN_SMEM_BYTES ((SM_Q + SM_K + SM_V) * (int)sizeof(float))   // 70656

__global__ __launch_bounds__(128, 2) void attn6_kernel(float* __restrict__ out)
{
    extern __shared__ float sm[];
    float* Qs  = sm;             // [128][QP] raw fp32 (pre-scaled)
    float* Khi = Qs + SM_Q;      // [64][KP] tf32-rounded fp32
    float* Vt  = Khi + SM_K;     // [64][VP] tf32-rounded fp32

    const int tid  = threadIdx.x;
    const int warp = tid >> 5;
    const int lane = tid & 31;
    const int g    = lane >> 2;
    const int t    = lane & 3;
    const int wm   = warp * 32;
    const int bh   = blockIdx.y;
    const int qt   = blockIdx.x;

    const float* Qg = g_Q + ((size_t)bh * S_ + qt * 128) * HD_;
    const float* Kg = g_K + (size_t)bh * S_ * HD_;
    const float* Vg = g_V + (size_t)bh * S_ * HD_;

    #pragma unroll
    for (int i = 0; i < 16; i++) {
        int idx = tid + i * 128;
        int row = idx >> 4;
        int col = (idx & 15) << 2;
        *(float4*)&Qs[row * QP + col] = *(const float4*)(Qg + row * HD_ + col);
    }

    float m[2][2], l[2][2];
    #pragma unroll
    for (int mf = 0; mf < 2; mf++) {
        m[mf][0] = -INFINITY; m[mf][1] = -INFINITY;
        l[mf][0] = 0.f;       l[mf][1] = 0.f;
    }
    float O[2][8][4];
    #pragma unroll
    for (int mf = 0; mf < 2; mf++)
        #pragma unroll
        for (int nt = 0; nt < 8; nt++)
            #pragma unroll
            for (int j = 0; j < 4; j++) O[mf][nt][j] = 0.f;

    for (int kt = 0; kt < S_ / 64; kt++) {
        __syncthreads();

        // ---- stage K and V: pure float4 copies (data already tf32) ----
        const float* Kt = Kg + (size_t)kt * 64 * HD_;
        const float* Vp = Vg + (size_t)kt * 64 * HD_;
        #pragma unroll
        for (int i = 0; i < 8; i++) {
            int idx = tid + i * 128;
            int row = idx >> 4;
            int col = (idx & 15) << 2;
            *(float4*)&Khi[row * KP + col] = *(const float4*)(Kt + row * HD_ + col);
            *(float4*)&Vt[row * VP + col]  = *(const float4*)(Vp + row * HD_ + col);
        }
        __syncthreads();

        // ---- scores (log2 domain): 2 MMAs (hi*hi + lo*hi) ----
        float Sf[2][8][4];
        #pragma unroll
        for (int mf = 0; mf < 2; mf++)
            #pragma unroll
            for (int nt = 0; nt < 8; nt++)
                #pragma unroll
                for (int j = 0; j < 4; j++) Sf[mf][nt][j] = 0.f;

        #pragma unroll
        for (int kc = 0; kc < 8; kc++) {
            uint32_t ah[2][4], al[2][4];
            #pragma unroll
            for (int mf = 0; mf < 2; mf++) {
                int qi = (wm + mf * 16 + g) * QP + kc * 8 + t;
                float a0f = Qs[qi];
                float a1f = Qs[qi + 8 * QP];
                float a2f = Qs[qi + 4];
                float a3f = Qs[qi + 8 * QP + 4];
                ah[mf][0] = f2tf(a0f); ah[mf][1] = f2tf(a1f);
                ah[mf][2] = f2tf(a2f); ah[mf][3] = f2tf(a3f);
                al[mf][0] = f2tf(a0f - __uint_as_float(ah[mf][0]));
                al[mf][1] = f2tf(a1f - __uint_as_float(ah[mf][1]));
                al[mf][2] = f2tf(a2f - __uint_as_float(ah[mf][2]));
                al[mf][3] = f2tf(a3f - __uint_as_float(ah[mf][3]));
            }
            #pragma unroll
            for (int nt = 0; nt < 8; nt++) {
                int kb = (nt * 8 + g) * KP + kc * 8 + t;
                uint32_t bh0 = __float_as_uint(Khi[kb]);
                uint32_t bh1 = __float_as_uint(Khi[kb + 4]);
                #pragma unroll
                for (int mf = 0; mf < 2; mf++) {
                    mma_tf32(Sf[mf][nt], ah[mf][0], ah[mf][1], ah[mf][2], ah[mf][3], bh0, bh1);
                    mma_tf32(Sf[mf][nt], al[mf][0], al[mf][1], al[mf][2], al[mf][3], bh0, bh1);
                }
            }
        }

        // ---- online softmax (base-2) ----
        #pragma unroll
        for (int mf = 0; mf < 2; mf++) {
            float mx0 = -INFINITY, mx1 = -INFINITY;
            #pragma unroll
            for (int nt = 0; nt < 8; nt++) {
                mx0 = fmaxf(mx0, fmaxf(Sf[mf][nt][0], Sf[mf][nt][1]));
                mx1 = fmaxf(mx1, fmaxf(Sf[mf][nt][2], Sf[mf][nt][3]));
            }
            mx0 = fmaxf(mx0, __shfl_xor_sync(0xffffffffu, mx0, 1));
            mx0 = fmaxf(mx0, __shfl_xor_sync(0xffffffffu, mx0, 2));
            mx1 = fmaxf(mx1, __shfl_xor_sync(0xffffffffu, mx1, 1));
            mx1 = fmaxf(mx1, __shfl_xor_sync(0xffffffffu, mx1, 2));

            float mn0 = fmaxf(m[mf][0], mx0);
            float mn1 = fmaxf(m[mf][1], mx1);
            float alp0 = ex2(m[mf][0] - mn0);
            float alp1 = ex2(m[mf][1] - mn1);

            float ls0 = 0.f, ls1 = 0.f;
            #pragma unroll
            for (int nt = 0; nt < 8; nt++) {
                Sf[mf][nt][0] = ex2(Sf[mf][nt][0] - mn0);
                Sf[mf][nt][1] = ex2(Sf[mf][nt][1] - mn0);
                Sf[mf][nt][2] = ex2(Sf[mf][nt][2] - mn1);
                Sf[mf][nt][3] = ex2(Sf[mf][nt][3] - mn1);
                ls0 += Sf[mf][nt][0] + Sf[mf][nt][1];
                ls1 += Sf[mf][nt][2] + Sf[mf][nt][3];
            }
            ls0 += __shfl_xor_sync(0xffffffffu, ls0, 1);
            ls0 += __shfl_xor_sync(0xffffffffu, ls0, 2);
            ls1 += __shfl_xor_sync(0xffffffffu, ls1, 1);
            ls1 += __shfl_xor_sync(0xffffffffu, ls1, 2);

            l[mf][0] = l[mf][0] * alp0 + ls0;  m[mf][0] = mn0;
            l[mf][1] = l[mf][1] * alp1 + ls1;  m[mf][1] = mn1;

            #pragma unroll
            for (int nt = 0; nt < 8; nt++) {
                O[mf][nt][0] *= alp0;  O[mf][nt][1] *= alp0;
                O[mf][nt][2] *= alp1;  O[mf][nt][3] *= alp1;
            }
        }

        // ---- O += P @ V ----
        const int src0 = (lane & ~3) + (t >> 1);
        const int src2 = src0 + 2;
        const bool odd = (t & 1);

        #pragma unroll
        for (int kc = 0; kc < 8; kc++) {
            uint32_t a[2][4];
            #pragma unroll
            for (int mf = 0; mf < 2; mf++) {
                float e0 = __shfl_sync(0xffffffffu, Sf[mf][kc][0], src0);
                float e1 = __shfl_sync(0xffffffffu, Sf[mf][kc][1], src0);
                float f0 = __shfl_sync(0xffffffffu, Sf[mf][kc][0], src2);
                float f1 = __shfl_sync(0xffffffffu, Sf[mf][kc][1], src2);
                float h0 = __shfl_sync(0xffffffffu, Sf[mf][kc][2], src0);
                float h1 = __shfl_sync(0xffffffffu, Sf[mf][kc][3], src0);
                float i0 = __shfl_sync(0xffffffffu, Sf[mf][kc][2], src2);
                float i1 = __shfl_sync(0xffffffffu, Sf[mf][kc][3], src2);
                a[mf][0] = f2tf(odd ? e1 : e0);
                a[mf][1] = f2tf(odd ? h1 : h0);
                a[mf][2] = f2tf(odd ? f1 : f0);
                a[mf][3] = f2tf(odd ? i1 : i0);
            }
            #pragma unroll
            for (int nt = 0; nt < 8; nt++) {
                int vi = (kc * 8 + t) * VP + nt * 8 + g;
                uint32_t bh0 = __float_as_uint(Vt[vi]);
                uint32_t bh1 = __float_as_uint(Vt[vi + 4 * VP]);
                #pragma unroll
                for (int mf = 0; mf < 2; mf++)
                    mma_tf32(O[mf][nt], a[mf][0], a[mf][1], a[mf][2], a[mf][3], bh0, bh1);
            }
        }
    }

    // ---- epilogue ----
    int b = bh >> 4;
    int h = bh & 15;
    #pragma unroll
    for (int mf = 0; mf < 2; mf++) {
        float inv0 = 1.f / l[mf][0];
        float inv1 = 1.f / l[mf][1];
        int srow = qt * 128 + wm + mf * 16 + g;
        size_t base0 = ((size_t)(b * S_ + srow) * H_ + h) * HD_;
        size_t base1 = base0 + (size_t)8 * H_ * HD_;
        #pragma unroll
        for (int nt = 0; nt < 8; nt++) {
            int col = nt * 8 + 2 * t;
            *(float2*)&out[base0 + col] =
                make_float2(O[mf][nt][0] * inv0, O[mf][nt][1] * inv0);
            *(float2*)&out[base1 + col] =
                make_float2(O[mf][nt][2] * inv1, O[mf][nt][3] * inv1);
        }
    }
}

extern "C" void kernel_launch(void* const* d_in, const int* in_sizes, int n_in,
                              void* d_out, int out_size)
{
    const float* hs = (const float*)d_in[0];
    const float* w  = (const float*)d_in[1];
    const float* qb = (const float*)d_in[2];
    const float* vb = (const float*)d_in[3];
    float* out = (float*)d_out;

    preconv_kernel<<<1792, 256>>>(hs, w);

    dim3 g1(N3_ / 128, M_ / 128);   // 24 x 32
    qkv_mma_kernel<<<g1, 256>>>(qb, vb);

    cudaFuncSetAttribute(attn6_kernel,
                         cudaFuncAttributeMaxDynamicSharedMemorySize, ATTN_SMEM_BYTES);
    dim3 g2(S_ / 128, B_ * H_);     // 16 x 32
    attn6_kernel<<<g2, 128, ATTN_SMEM_BYTES>>>(out);
}

// round 9
// speedup vs baseline: 1.3712x; 1.2139x over previous
#include <cuda_runtime.h>
#include <math.h>
#include <stdint.h>

#define B_  2
#define S_  2048
#define D_  1024
#define H_  16
#define HD_ 64
#define M_  (B_ * S_)    // 4096
#define N3_ (3 * D_)     // 3072

// Scratch for Q/K/V in (b*H+h, s, e) layout.
__device__ float g_Q[(size_t)M_ * D_];      // raw fp32, pre-scaled by QSCALE
__device__ float g_K[(size_t)M_ * D_];      // tf32-rounded
__device__ float g_V[(size_t)M_ * D_];      // tf32-rounded

// ---------------------------------------------------------------------------
// TF32 helpers
// ---------------------------------------------------------------------------
__device__ __forceinline__ uint32_t f2tf(float x) {
    uint32_t r;
    asm("cvt.rna.tf32.f32 %0, %1;" : "=r"(r) : "f"(x));
    return r;
}
__device__ __forceinline__ float tf32r(float x) {
    uint32_t r;
    asm("cvt.rna.tf32.f32 %0, %1;" : "=r"(r) : "f"(x));
    return __uint_as_float(r);
}
__device__ __forceinline__ float ex2(float x) {
    float r;
    asm("ex2.approx.f32 %0, %1;" : "=f"(r) : "f"(x));
    return r;
}
__device__ __forceinline__ void mma_tf32(float c[4],
    uint32_t a0, uint32_t a1, uint32_t a2, uint32_t a3,
    uint32_t b0, uint32_t b1)
{
    asm volatile(
        "mma.sync.aligned.m16n8k8.row.col.f32.tf32.tf32.f32 "
        "{%0,%1,%2,%3}, {%4,%5,%6,%7}, {%8,%9}, {%0,%1,%2,%3};"
        : "+f"(c[0]), "+f"(c[1]), "+f"(c[2]), "+f"(c[3])
        : "r"(a0), "r"(a1), "r"(a2), "r"(a3), "r"(b0), "r"(b1));
}

// Q scale: 1/sqrt(64) * log2(e) -> scores in log2 domain, softmax via ex2
#define QSCALE 0.1803368801111204f

// ---------------------------------------------------------------------------
// Kernel 1: QKV projection, split-TF32 MMA — the PROVEN round-4 kernel
// (measured ~450-457us twice). Convert-in-kernel, separate hi/lo buffers,
// reg prefetch, 2 syncs/slab. Only the epilogue differs: Q*QSCALE,
// K/V tf32-rounded for attn's pure-copy staging.
// BM=128, BN=128, BK=16, 256 threads, warps 4(M)x2(N), warp tile 32x64.
// ---------------------------------------------------------------------------
#define GP_A 20
#define GP_W 136

__global__ __launch_bounds__(256, 2) void qkv_mma_kernel(
    const float* __restrict__ A, const float* __restrict__ W,
    const float* __restrict__ qbias, const float* __restrict__ vbias)
{
    __shared__ float Ahi[128 * GP_A], Alo[128 * GP_A];
    __shared__ float Whi[16 * GP_W],  Wlo[16 * GP_W];

    const int tid  = threadIdx.x;
    const int warp = tid >> 5;
    const int lane = tid & 31;
    const int g    = lane >> 2;
    const int t    = lane & 3;
    const int bm   = blockIdx.y * 128;
    const int bn   = blockIdx.x * 128;
    const int warpM = (warp >> 1) * 32;
    const int warpN = (warp & 1) * 64;

    float C[2][8][4];
    #pragma unroll
    for (int mf = 0; mf < 2; mf++)
        #pragma unroll
        for (int nf = 0; nf < 8; nf++)
            #pragma unroll
            for (int j = 0; j < 4; j++) C[mf][nf][j] = 0.f;

    int arow[2], acg[2], wkk[2], wnn[2];
    float4 pa[2], pw[2];
    #pragma unroll
    for (int i = 0; i < 2; i++) {
        int idx = tid + i * 256;
        arow[i] = idx >> 2;
        acg[i]  = (idx & 3) << 2;
        wkk[i]  = idx >> 5;
        wnn[i]  = (idx & 31) << 2;
        pa[i] = *(const float4*)(A + (size_t)(bm + arow[i]) * D_ + acg[i]);
        pw[i] = *(const float4*)(W + (size_t)wkk[i] * N3_ + bn + wnn[i]);
    }

    for (int k0 = 0; k0 < D_ / 16; k0++) {
        __syncthreads();

        #pragma unroll
        for (int i = 0; i < 2; i++) {
            float4 x = pa[i];
            float4 hi = make_float4(tf32r(x.x), tf32r(x.y), tf32r(x.z), tf32r(x.w));
            float4 lo = make_float4(tf32r(x.x - hi.x), tf32r(x.y - hi.y),
                                    tf32r(x.z - hi.z), tf32r(x.w - hi.w));
            *(float4*)&Ahi[arow[i] * GP_A + acg[i]] = hi;
            *(float4*)&Alo[arow[i] * GP_A + acg[i]] = lo;

            float4 y = pw[i];
            float4 whi = make_float4(tf32r(y.x), tf32r(y.y), tf32r(y.z), tf32r(y.w));
            float4 wlo = make_float4(tf32r(y.x - whi.x), tf32r(y.y - whi.y),
                                     tf32r(y.z - whi.z), tf32r(y.w - whi.w));
            *(float4*)&Whi[wkk[i] * GP_W + wnn[i]] = whi;
            *(float4*)&Wlo[wkk[i] * GP_W + wnn[i]] = wlo;
        }
        __syncthreads();

        if (k0 < D_ / 16 - 1) {
            #pragma unroll
            for (int i = 0; i < 2; i++) {
                pa[i] = *(const float4*)(A + (size_t)(bm + arow[i]) * D_
                                           + (k0 + 1) * 16 + acg[i]);
                pw[i] = *(const float4*)(W + (size_t)((k0 + 1) * 16 + wkk[i]) * N3_
                                           + bn + wnn[i]);
            }
        }

        #pragma unroll
        for (int kc = 0; kc < 2; kc++) {
            uint32_t ah[2][4], al[2][4];
            #pragma unroll
            for (int mf = 0; mf < 2; mf++) {
                int r0 = (warpM + mf * 16 + g) * GP_A + kc * 8 + t;
                ah[mf][0] = __float_as_uint(Ahi[r0]);
                ah[mf][1] = __float_as_uint(Ahi[r0 + 8 * GP_A]);
                ah[mf][2] = __float_as_uint(Ahi[r0 + 4]);
                ah[mf][3] = __float_as_uint(Ahi[r0 + 8 * GP_A + 4]);
                al[mf][0] = __float_as_uint(Alo[r0]);
                al[mf][1] = __float_as_uint(Alo[r0 + 8 * GP_A]);
                al[mf][2] = __float_as_uint(Alo[r0 + 4]);
                al[mf][3] = __float_as_uint(Alo[r0 + 8 * GP_A + 4]);
            }
            #pragma unroll
            for (int nf = 0; nf < 8; nf++) {
                int n  = warpN + nf * 8 + g;
                int kb = (kc * 8 + t) * GP_W + n;
                uint32_t bh0 = __float_as_uint(Whi[kb]);
                uint32_t bh1 = __float_as_uint(Whi[kb + 4 * GP_W]);
                uint32_t bl0 = __float_as_uint(Wlo[kb]);
                uint32_t bl1 = __float_as_uint(Wlo[kb + 4 * GP_W]);
                #pragma unroll
                for (int mf = 0; mf < 2; mf++) {
                    mma_tf32(C[mf][nf], ah[mf][0], ah[mf][1], ah[mf][2], ah[mf][3], bh0, bh1);
                    mma_tf32(C[mf][nf], ah[mf][0], ah[mf][1], ah[mf][2], ah[mf][3], bl0, bl1);
                    mma_tf32(C[mf][nf], al[mf][0], al[mf][1], al[mf][2], al[mf][3], bh0, bh1);
                }
            }
        }
    }

    // Epilogue: scatter into (b*H+h, s, e); Q raw*QSCALE, K/V tf32-rounded.
    const int which = bn >> 10;
    #pragma unroll
    for (int mf = 0; mf < 2; mf++) {
        int mrow = bm + warpM + mf * 16 + g;
        int b = mrow >> 11;
        int s = mrow & (S_ - 1);
        #pragma unroll
        for (int nf = 0; nf < 8; nf++) {
            int ncol = bn + warpN + nf * 8 + 2 * t;
            int d = ncol & (D_ - 1);
            int h = d >> 6;
            int e = d & 63;
            size_t i0 = ((size_t)(b * H_ + h) * S_ + s) * HD_ + e;
            size_t i1 = i0 + 8 * HD_;
            float c0 = C[mf][nf][0], c1 = C[mf][nf][1];
            float c2 = C[mf][nf][2], c3 = C[mf][nf][3];
            if (which == 0) {
                float b0 = qbias[d], b1 = qbias[d + 1];
                *(float2*)&g_Q[i0] = make_float2((c0 + b0) * QSCALE, (c1 + b1) * QSCALE);
                *(float2*)&g_Q[i1] = make_float2((c2 + b0) * QSCALE, (c3 + b1) * QSCALE);
            } else if (which == 1) {
                *(float2*)&g_K[i0] = make_float2(tf32r(c0), tf32r(c1));
                *(float2*)&g_K[i1] = make_float2(tf32r(c2), tf32r(c3));
            } else {
                float b0 = vbias[d], b1 = vbias[d + 1];
                *(float2*)&g_V[i0] = make_float2(tf32r(c0 + b0), tf32r(c1 + b1));
                *(float2*)&g_V[i1] = make_float2(tf32r(c2 + b0), tf32r(c3 + b1));
            }
        }
    }
}

// ---------------------------------------------------------------------------
// Kernel 2: flash attention, TF32 MMA (round-8 attn6, unchanged).
// Block = 128 threads (4 warps), warp tile M=32, Br=128, Bc=64.
// QK = 2 MMAs (q_hi*k_hi + q_lo*k_hi); K/V arrive tf32-rounded from qkv,
// staging is pure copies. Softmax in log2 domain via ex2.
// smem: Qs [128][68] + Khi [64][68] + Vt [64][72] = 70656 B -> 2 blk/SM.
// ---------------------------------------------------------------------------
#define QP 68
#define KP 68
#define VP 72
#define SM_Q (128 * QP)
#define SM_K (64 * KP)
#define SM_V (64 * VP)
#define ATTN_SMEM_BYTES ((SM_Q + SM_K + SM_V) * (int)sizeof(float))   // 70656

__global__ __launch_bounds__(128, 2) void attn6_kernel(float* __restrict__ out)
{
    extern __shared__ float sm[];
    float* Qs  = sm;             // [128][QP] raw fp32 (pre-scaled)
    float* Khi = Qs + SM_Q;      // [64][KP] tf32-rounded fp32
    float* Vt  = Khi + SM_K;     // [64][VP] tf32-rounded fp32

    const int tid  = threadIdx.x;
    const int warp = tid >> 5;
    const int lane = tid & 31;
    const int g    = lane >> 2;
    const int t    = lane & 3;
    const int wm   = warp * 32;
    const int bh   = blockIdx.y;
    const int qt   = blockIdx.x;

    const float* Qg = g_Q + ((size_t)bh * S_ + qt * 128) * HD_;
    const float* Kg = g_K + (size_t)bh * S_ * HD_;
    const float* Vg = g_V + (size_t)bh * S_ * HD_;

    #pragma unroll
    for (int i = 0; i < 16; i++) {
        int idx = tid + i * 128;
        int row = idx >> 4;
        int col = (idx & 15) << 2;
        *(float4*)&Qs[row * QP + col] = *(const float4*)(Qg + row * HD_ + col);
    }

    float m[2][2], l[2][2];
    #pragma unroll
    for (int mf = 0; mf < 2; mf++) {
        m[mf][0] = -INFINITY; m[mf][1] = -INFINITY;
        l[mf][0] = 0.f;       l[mf][1] = 0.f;
    }
    float O[2][8][4];
    #pragma unroll
    for (int mf = 0; mf < 2; mf++)
        #pragma unroll
        for (int nt = 0; nt < 8; nt++)
            #pragma unroll
            for (int j = 0; j < 4; j++) O[mf][nt][j] = 0.f;

    for (int kt = 0; kt < S_ / 64; kt++) {
        __syncthreads();

        // ---- stage K and V: pure float4 copies (data already tf32) ----
        const float* Kt = Kg + (size_t)kt * 64 * HD_;
        const float* Vp = Vg + (size_t)kt * 64 * HD_;
        #pragma unroll
        for (int i = 0; i < 8; i++) {
            int idx = tid + i * 128;
            int row = idx >> 4;
            int col = (idx & 15) << 2;
            *(float4*)&Khi[row * KP + col] = *(const float4*)(Kt + row * HD_ + col);
            *(float4*)&Vt[row * VP + col]  = *(const float4*)(Vp + row * HD_ + col);
        }
        __syncthreads();

        // ---- scores (log2 domain): 2 MMAs (hi*hi + lo*hi) ----
        float Sf[2][8][4];
        #pragma unroll
        for (int mf = 0; mf < 2; mf++)
            #pragma unroll
            for (int nt = 0; nt < 8; nt++)
                #pragma unroll
                for (int j = 0; j < 4; j++) Sf[mf][nt][j] = 0.f;

        #pragma unroll
        for (int kc = 0; kc < 8; kc++) {
            uint32_t ah[2][4], al[2][4];
            #pragma unroll
            for (int mf = 0; mf < 2; mf++) {
                int qi = (wm + mf * 16 + g) * QP + kc * 8 + t;
                float a0f = Qs[qi];
                float a1f = Qs[qi + 8 * QP];
                float a2f = Qs[qi + 4];
                float a3f = Qs[qi + 8 * QP + 4];
                ah[mf][0] = f2tf(a0f); ah[mf][1] = f2tf(a1f);
                ah[mf][2] = f2tf(a2f); ah[mf][3] = f2tf(a3f);
                al[mf][0] = f2tf(a0f - __uint_as_float(ah[mf][0]));
                al[mf][1] = f2tf(a1f - __uint_as_float(ah[mf][1]));
                al[mf][2] = f2tf(a2f - __uint_as_float(ah[mf][2]));
                al[mf][3] = f2tf(a3f - __uint_as_float(ah[mf][3]));
            }
            #pragma unroll
            for (int nt = 0; nt < 8; nt++) {
                int kb = (nt * 8 + g) * KP + kc * 8 + t;
                uint32_t bh0 = __float_as_uint(Khi[kb]);
                uint32_t bh1 = __float_as_uint(Khi[kb + 4]);
                #pragma unroll
                for (int mf = 0; mf < 2; mf++) {
                    mma_tf32(Sf[mf][nt], ah[mf][0], ah[mf][1], ah[mf][2], ah[mf][3], bh0, bh1);
                    mma_tf32(Sf[mf][nt], al[mf][0], al[mf][1], al[mf][2], al[mf][3], bh0, bh1);
                }
            }
        }

        // ---- online softmax (base-2) ----
        #pragma unroll
        for (int mf = 0; mf < 2; mf++) {
            float mx0 = -INFINITY, mx1 = -INFINITY;
            #pragma unroll
            for (int nt = 0; nt < 8; nt++) {
                mx0 = fmaxf(mx0, fmaxf(Sf[mf][nt][0], Sf[mf][nt][1]));
                mx1 = fmaxf(mx1, fmaxf(Sf[mf][nt][2], Sf[mf][nt][3]));
            }
            mx0 = fmaxf(mx0, __shfl_xor_sync(0xffffffffu, mx0, 1));
            mx0 = fmaxf(mx0, __shfl_xor_sync(0xffffffffu, mx0, 2));
            mx1 = fmaxf(mx1, __shfl_xor_sync(0xffffffffu, mx1, 1));
            mx1 = fmaxf(mx1, __shfl_xor_sync(0xffffffffu, mx1, 2));

            float mn0 = fmaxf(m[mf][0], mx0);
            float mn1 = fmaxf(m[mf][1], mx1);
            float alp0 = ex2(m[mf][0] - mn0);
            float alp1 = ex2(m[mf][1] - mn1);

            float ls0 = 0.f, ls1 = 0.f;
            #pragma unroll
            for (int nt = 0; nt < 8; nt++) {
                Sf[mf][nt][0] = ex2(Sf[mf][nt][0] - mn0);
                Sf[mf][nt][1] = ex2(Sf[mf][nt][1] - mn0);
                Sf[mf][nt][2] = ex2(Sf[mf][nt][2] - mn1);
                Sf[mf][nt][3] = ex2(Sf[mf][nt][3] - mn1);
                ls0 += Sf[mf][nt][0] + Sf[mf][nt][1];
                ls1 += Sf[mf][nt][2] + Sf[mf][nt][3];
            }
            ls0 += __shfl_xor_sync(0xffffffffu, ls0, 1);
            ls0 += __shfl_xor_sync(0xffffffffu, ls0, 2);
            ls1 += __shfl_xor_sync(0xffffffffu, ls1, 1);
            ls1 += __shfl_xor_sync(0xffffffffu, ls1, 2);

            l[mf][0] = l[mf][0] * alp0 + ls0;  m[mf][0] = mn0;
            l[mf][1] = l[mf][1] * alp1 + ls1;  m[mf][1] = mn1;

            #pragma unroll
            for (int nt = 0; nt < 8; nt++) {
                O[mf][nt][0] *= alp0;  O[mf][nt][1] *= alp0;
                O[mf][nt][2] *= alp1;  O[mf][nt][3] *= alp1;
            }
        }

        // ---- O += P @ V ----
        const int src0 = (lane & ~3) + (t >> 1);
        const int src2 = src0 + 2;
        const bool odd = (t & 1);

        #pragma unroll
        for (int kc = 0; kc < 8; kc++) {
            uint32_t a[2][4];
            #pragma unroll
            for (int mf = 0; mf < 2; mf++) {
                float e0 = __shfl_sync(0xffffffffu, Sf[mf][kc][0], src0);
                float e1 = __shfl_sync(0xffffffffu, Sf[mf][kc][1], src0);
                float f0 = __shfl_sync(0xffffffffu, Sf[mf][kc][0], src2);
                float f1 = __shfl_sync(0xffffffffu, Sf[mf][kc][1], src2);
                float h0 = __shfl_sync(0xffffffffu, Sf[mf][kc][2], src0);
                float h1 = __shfl_sync(0xffffffffu, Sf[mf][kc][3], src0);
                float i0 = __shfl_sync(0xffffffffu, Sf[mf][kc][2], src2);
                float i1 = __shfl_sync(0xffffffffu, Sf[mf][kc][3], src2);
                a[mf][0] = f2tf(odd ? e1 : e0);
                a[mf][1] = f2tf(odd ? h1 : h0);
                a[mf][2] = f2tf(odd ? f1 : f0);
                a[mf][3] = f2tf(odd ? i1 : i0);
            }
            #pragma unroll
            for (int nt = 0; nt < 8; nt++) {
                int vi = (kc * 8 + t) * VP + nt * 8 + g;
                uint32_t bh0 = __float_as_uint(Vt[vi]);
                uint32_t bh1 = __float_as_uint(Vt[vi + 4 * VP]);
                #pragma unroll
                for (int mf = 0; mf < 2; mf++)
                    mma_tf32(O[mf][nt], a[mf][0], a[mf][1], a[mf][2], a[mf][3], bh0, bh1);
            }
        }
    }

    // ---- epilogue ----
    int b = bh >> 4;
    int h = bh & 15;
    #pragma unroll
    for (int mf = 0; mf < 2; mf++) {
        float inv0 = 1.f / l[mf][0];
        float inv1 = 1.f / l[mf][1];
        int srow = qt * 128 + wm + mf * 16 + g;
        size_t base0 = ((size_t)(b * S_ + srow) * H_ + h) * HD_;
        size_t base1 = base0 + (size_t)8 * H_ * HD_;
        #pragma unroll
        for (int nt = 0; nt < 8; nt++) {
            int col = nt * 8 + 2 * t;
            *(float2*)&out[base0 + col] =
                make_float2(O[mf][nt][0] * inv0, O[mf][nt][1] * inv0);
            *(float2*)&out[base1 + col] =
                make_float2(O[mf][nt][2] * inv1, O[mf][nt][3] * inv1);
        }
    }
}

extern "C" void kernel_launch(void* const* d_in, const int* in_sizes, int n_in,
                              void* d_out, int out_size)
{
    const float* hs = (const float*)d_in[0];
    const float* w  = (const float*)d_in[1];
    const float* qb = (const float*)d_in[2];
    const float* vb = (const float*)d_in[3];
    float* out = (float*)d_out;

    dim3 g1(N3_ / 128, M_ / 128);   // 24 x 32
    qkv_mma_kernel<<<g1, 256>>>(hs, w, qb, vb);

    cudaFuncSetAttribute(attn6_kernel,
                         cudaFuncAttributeMaxDynamicSharedMemorySize, ATTN_SMEM_BYTES);
    dim3 g2(S_ / 128, B_ * H_);     // 16 x 32
    attn6_kernel<<<g2, 128, ATTN_SMEM_BYTES>>>(out);
}

// round 10
// speedup vs baseline: 1.5905x; 1.1599x over previous
#include <cuda_runtime.h>
#include <math.h>
#include <stdint.h>

#define B_  2
#define S_  2048
#define D_  1024
#define H_  16
#define HD_ 64
#define M_  (B_ * S_)    // 4096
#define N3_ (3 * D_)     // 3072

// Scratch for Q/K/V in (b*H+h, s, e) layout.
__device__ float g_Q[(size_t)M_ * D_];      // raw fp32, pre-scaled by QSCALE
__device__ float g_K[(size_t)M_ * D_];      // tf32-rounded
__device__ float g_V[(size_t)M_ * D_];      // tf32-rounded

// ---------------------------------------------------------------------------
// TF32 helpers
// ---------------------------------------------------------------------------
__device__ __forceinline__ uint32_t f2tf(float x) {
    uint32_t r;
    asm("cvt.rna.tf32.f32 %0, %1;" : "=r"(r) : "f"(x));
    return r;
}
__device__ __forceinline__ float tf32r(float x) {
    uint32_t r;
    asm("cvt.rna.tf32.f32 %0, %1;" : "=r"(r) : "f"(x));
    return __uint_as_float(r);
}
__device__ __forceinline__ float ex2(float x) {
    float r;
    asm("ex2.approx.f32 %0, %1;" : "=f"(r) : "f"(x));
    return r;
}
__device__ __forceinline__ void mma_tf32(float c[4],
    uint32_t a0, uint32_t a1, uint32_t a2, uint32_t a3,
    uint32_t b0, uint32_t b1)
{
    asm volatile(
        "mma.sync.aligned.m16n8k8.row.col.f32.tf32.tf32.f32 "
        "{%0,%1,%2,%3}, {%4,%5,%6,%7}, {%8,%9}, {%0,%1,%2,%3};"
        : "+f"(c[0]), "+f"(c[1]), "+f"(c[2]), "+f"(c[3])
        : "r"(a0), "r"(a1), "r"(a2), "r"(a3), "r"(b0), "r"(b1));
}

// Q scale: 1/sqrt(64) * log2(e) -> scores in log2 domain, softmax via ex2
#define QSCALE 0.1803368801111204f

// ---------------------------------------------------------------------------
// Kernel 1: QKV projection, 2-MMA split-TF32 (a_hi*w_hi + a_lo*w_hi).
// Round-4 skeleton (convert-in-kernel, reg prefetch, 2 syncs/slab) with the
// W-lo buffer/term removed: W is used tf32-rounded. A stays hi/lo split.
// BM=128, BN=128, BK=16, 256 threads, warps 4(M)x2(N), warp tile 32x64.
// ---------------------------------------------------------------------------
#define GP_A 20
#define GP_W 136

__global__ __launch_bounds__(256, 2) void qkv_mma_kernel(
    const float* __restrict__ A, const float* __restrict__ W,
    const float* __restrict__ qbias, const float* __restrict__ vbias)
{
    __shared__ float Ahi[128 * GP_A], Alo[128 * GP_A];   // 2x10240 B
    __shared__ float Whi[16 * GP_W];                      // 8704 B

    const int tid  = threadIdx.x;
    const int warp = tid >> 5;
    const int lane = tid & 31;
    const int g    = lane >> 2;
    const int t    = lane & 3;
    const int bm   = blockIdx.y * 128;
    const int bn   = blockIdx.x * 128;
    const int warpM = (warp >> 1) * 32;
    const int warpN = (warp & 1) * 64;

    float C[2][8][4];
    #pragma unroll
    for (int mf = 0; mf < 2; mf++)
        #pragma unroll
        for (int nf = 0; nf < 8; nf++)
            #pragma unroll
            for (int j = 0; j < 4; j++) C[mf][nf][j] = 0.f;

    int arow[2], acg[2], wkk[2], wnn[2];
    float4 pa[2], pw[2];
    #pragma unroll
    for (int i = 0; i < 2; i++) {
        int idx = tid + i * 256;
        arow[i] = idx >> 2;
        acg[i]  = (idx & 3) << 2;
        wkk[i]  = idx >> 5;
        wnn[i]  = (idx & 31) << 2;
        pa[i] = *(const float4*)(A + (size_t)(bm + arow[i]) * D_ + acg[i]);
        pw[i] = *(const float4*)(W + (size_t)wkk[i] * N3_ + bn + wnn[i]);
    }

    for (int k0 = 0; k0 < D_ / 16; k0++) {
        __syncthreads();

        #pragma unroll
        for (int i = 0; i < 2; i++) {
            float4 x = pa[i];
            float4 hi = make_float4(tf32r(x.x), tf32r(x.y), tf32r(x.z), tf32r(x.w));
            float4 lo = make_float4(tf32r(x.x - hi.x), tf32r(x.y - hi.y),
                                    tf32r(x.z - hi.z), tf32r(x.w - hi.w));
            *(float4*)&Ahi[arow[i] * GP_A + acg[i]] = hi;
            *(float4*)&Alo[arow[i] * GP_A + acg[i]] = lo;

            float4 y = pw[i];
            *(float4*)&Whi[wkk[i] * GP_W + wnn[i]] =
                make_float4(tf32r(y.x), tf32r(y.y), tf32r(y.z), tf32r(y.w));
        }
        __syncthreads();

        if (k0 < D_ / 16 - 1) {
            #pragma unroll
            for (int i = 0; i < 2; i++) {
                pa[i] = *(const float4*)(A + (size_t)(bm + arow[i]) * D_
                                           + (k0 + 1) * 16 + acg[i]);
                pw[i] = *(const float4*)(W + (size_t)((k0 + 1) * 16 + wkk[i]) * N3_
                                           + bn + wnn[i]);
            }
        }

        #pragma unroll
        for (int kc = 0; kc < 2; kc++) {
            uint32_t ah[2][4], al[2][4];
            #pragma unroll
            for (int mf = 0; mf < 2; mf++) {
                int r0 = (warpM + mf * 16 + g) * GP_A + kc * 8 + t;
                ah[mf][0] = __float_as_uint(Ahi[r0]);
                ah[mf][1] = __float_as_uint(Ahi[r0 + 8 * GP_A]);
                ah[mf][2] = __float_as_uint(Ahi[r0 + 4]);
                ah[mf][3] = __float_as_uint(Ahi[r0 + 8 * GP_A + 4]);
                al[mf][0] = __float_as_uint(Alo[r0]);
                al[mf][1] = __float_as_uint(Alo[r0 + 8 * GP_A]);
                al[mf][2] = __float_as_uint(Alo[r0 + 4]);
                al[mf][3] = __float_as_uint(Alo[r0 + 8 * GP_A + 4]);
            }
            #pragma unroll
            for (int nf = 0; nf < 8; nf++) {
                int n  = warpN + nf * 8 + g;
                int kb = (kc * 8 + t) * GP_W + n;
                uint32_t bh0 = __float_as_uint(Whi[kb]);
                uint32_t bh1 = __float_as_uint(Whi[kb + 4 * GP_W]);
                #pragma unroll
                for (int mf = 0; mf < 2; mf++) {
                    mma_tf32(C[mf][nf], ah[mf][0], ah[mf][1], ah[mf][2], ah[mf][3], bh0, bh1);
                    mma_tf32(C[mf][nf], al[mf][0], al[mf][1], al[mf][2], al[mf][3], bh0, bh1);
                }
            }
        }
    }

    // Epilogue: scatter into (b*H+h, s, e); Q raw*QSCALE, K/V tf32-rounded.
    const int which = bn >> 10;
    #pragma unroll
    for (int mf = 0; mf < 2; mf++) {
        int mrow = bm + warpM + mf * 16 + g;
        int b = mrow >> 11;
        int s = mrow & (S_ - 1);
        #pragma unroll
        for (int nf = 0; nf < 8; nf++) {
            int ncol = bn + warpN + nf * 8 + 2 * t;
            int d = ncol & (D_ - 1);
            int h = d >> 6;
            int e = d & 63;
            size_t i0 = ((size_t)(b * H_ + h) * S_ + s) * HD_ + e;
            size_t i1 = i0 + 8 * HD_;
            float c0 = C[mf][nf][0], c1 = C[mf][nf][1];
            float c2 = C[mf][nf][2], c3 = C[mf][nf][3];
            if (which == 0) {
                float b0 = qbias[d], b1 = qbias[d + 1];
                *(float2*)&g_Q[i0] = make_float2((c0 + b0) * QSCALE, (c1 + b1) * QSCALE);
                *(float2*)&g_Q[i1] = make_float2((c2 + b0) * QSCALE, (c3 + b1) * QSCALE);
            } else if (which == 1) {
                *(float2*)&g_K[i0] = make_float2(tf32r(c0), tf32r(c1));
                *(float2*)&g_K[i1] = make_float2(tf32r(c2), tf32r(c3));
            } else {
                float b0 = vbias[d], b1 = vbias[d + 1];
                *(float2*)&g_V[i0] = make_float2(tf32r(c0 + b0), tf32r(c1 + b1));
                *(float2*)&g_V[i1] = make_float2(tf32r(c2 + b0), tf32r(c3 + b1));
            }
        }
    }
}

// ---------------------------------------------------------------------------
// Kernel 2: flash attention, TF32 MMA (round-9 attn6, UNCHANGED — it matched
// prediction exactly; protect it).
// Block = 128 threads (4 warps), warp tile M=32, Br=128, Bc=64.
// QK = 2 MMAs (q_hi*k_hi + q_lo*k_hi); K/V arrive tf32-rounded from qkv,
// staging is pure copies. Softmax in log2 domain via ex2.
// smem: Qs [128][68] + Khi [64][68] + Vt [64][72] = 70656 B -> 2 blk/SM.
// ---------------------------------------------------------------------------
#define QP 68
#define KP 68
#define VP 72
#define SM_Q (128 * QP)
#define SM_K (64 * KP)
#define SM_V (64 * VP)
#define ATTN_SMEM_BYTES ((SM_Q + SM_K + SM_V) * (int)sizeof(float))   // 70656

__global__ __launch_bounds__(128, 2) void attn6_kernel(float* __restrict__ out)
{
    extern __shared__ float sm[];
    float* Qs  = sm;             // [128][QP] raw fp32 (pre-scaled)
    float* Khi = Qs + SM_Q;      // [64][KP] tf32-rounded fp32
    float* Vt  = Khi + SM_K;     // [64][VP] tf32-rounded fp32

    const int tid  = threadIdx.x;
    const int warp = tid >> 5;
    const int lane = tid & 31;
    const int g    = lane >> 2;
    const int t    = lane & 3;
    const int wm   = warp * 32;
    const int bh   = blockIdx.y;
    const int qt   = blockIdx.x;

    const float* Qg = g_Q + ((size_t)bh * S_ + qt * 128) * HD_;
    const float* Kg = g_K + (size_t)bh * S_ * HD_;
    const float* Vg = g_V + (size_t)bh * S_ * HD_;

    #pragma unroll
    for (int i = 0; i < 16; i++) {
        int idx = tid + i * 128;
        int row = idx >> 4;
        int col = (idx & 15) << 2;
        *(float4*)&Qs[row * QP + col] = *(const float4*)(Qg + row * HD_ + col);
    }

    float m[2][2], l[2][2];
    #pragma unroll
    for (int mf = 0; mf < 2; mf++) {
        m[mf][0] = -INFINITY; m[mf][1] = -INFINITY;
        l[mf][0] = 0.f;       l[mf][1] = 0.f;
    }
    float O[2][8][4];
    #pragma unroll
    for (int mf = 0; mf < 2; mf++)
        #pragma unroll
        for (int nt = 0; nt < 8; nt++)
            #pragma unroll
            for (int j = 0; j < 4; j++) O[mf][nt][j] = 0.f;

    for (int kt = 0; kt < S_ / 64; kt++) {
        __syncthreads();

        // ---- stage K and V: pure float4 copies (data already tf32) ----
        const float* Kt = Kg + (size_t)kt * 64 * HD_;
        const float* Vp = Vg + (size_t)kt * 64 * HD_;
        #pragma unroll
        for (int i = 0; i < 8; i++) {
            int idx = tid + i * 128;
            int row = idx >> 4;
            int col = (idx & 15) << 2;
            *(float4*)&Khi[row * KP + col] = *(const float4*)(Kt + row * HD_ + col);
            *(float4*)&Vt[row * VP + col]  = *(const float4*)(Vp + row * HD_ + col);
        }
        __syncthreads();

        // ---- scores (log2 domain): 2 MMAs (hi*hi + lo*hi) ----
        float Sf[2][8][4];
        #pragma unroll
        for (int mf = 0; mf < 2; mf++)
            #pragma unroll
            for (int nt = 0; nt < 8; nt++)
                #pragma unroll
                for (int j = 0; j < 4; j++) Sf[mf][nt][j] = 0.f;

        #pragma unroll
        for (int kc = 0; kc < 8; kc++) {
            uint32_t ah[2][4], al[2][4];
            #pragma unroll
            for (int mf = 0; mf < 2; mf++) {
                int qi = (wm + mf * 16 + g) * QP + kc * 8 + t;
                float a0f = Qs[qi];
                float a1f = Qs[qi + 8 * QP];
                float a2f = Qs[qi + 4];
                float a3f = Qs[qi + 8 * QP + 4];
                ah[mf][0] = f2tf(a0f); ah[mf][1] = f2tf(a1f);
                ah[mf][2] = f2tf(a2f); ah[mf][3] = f2tf(a3f);
                al[mf][0] = f2tf(a0f - __uint_as_float(ah[mf][0]));
                al[mf][1] = f2tf(a1f - __uint_as_float(ah[mf][1]));
                al[mf][2] = f2tf(a2f - __uint_as_float(ah[mf][2]));
                al[mf][3] = f2tf(a3f - __uint_as_float(ah[mf][3]));
            }
            #pragma unroll
            for (int nt = 0; nt < 8; nt++) {
                int kb = (nt * 8 + g) * KP + kc * 8 + t;
                uint32_t bh0 = __float_as_uint(Khi[kb]);
                uint32_t bh1 = __float_as_uint(Khi[kb + 4]);
                #pragma unroll
                for (int mf = 0; mf < 2; mf++) {
                    mma_tf32(Sf[mf][nt], ah[mf][0], ah[mf][1], ah[mf][2], ah[mf][3], bh0, bh1);
                    mma_tf32(Sf[mf][nt], al[mf][0], al[mf][1], al[mf][2], al[mf][3], bh0, bh1);
                }
            }
        }

        // ---- online softmax (base-2) ----
        #pragma unroll
        for (int mf = 0; mf < 2; mf++) {
            float mx0 = -INFINITY, mx1 = -INFINITY;
            #pragma unroll
            for (int nt = 0; nt < 8; nt++) {
                mx0 = fmaxf(mx0, fmaxf(Sf[mf][nt][0], Sf[mf][nt][1]));
                mx1 = fmaxf(mx1, fmaxf(Sf[mf][nt][2], Sf[mf][nt][3]));
            }
            mx0 = fmaxf(mx0, __shfl_xor_sync(0xffffffffu, mx0, 1));
            mx0 = fmaxf(mx0, __shfl_xor_sync(0xffffffffu, mx0, 2));
            mx1 = fmaxf(mx1, __shfl_xor_sync(0xffffffffu, mx1, 1));
            mx1 = fmaxf(mx1, __shfl_xor_sync(0xffffffffu, mx1, 2));

            float mn0 = fmaxf(m[mf][0], mx0);
            float mn1 = fmaxf(m[mf][1], mx1);
            float alp0 = ex2(m[mf][0] - mn0);
            float alp1 = ex2(m[mf][1] - mn1);

            float ls0 = 0.f, ls1 = 0.f;
            #pragma unroll
            for (int nt = 0; nt < 8; nt++) {
                Sf[mf][nt][0] = ex2(Sf[mf][nt][0] - mn0);
                Sf[mf][nt][1] = ex2(Sf[mf][nt][1] - mn0);
                Sf[mf][nt][2] = ex2(Sf[mf][nt][2] - mn1);
                Sf[mf][nt][3] = ex2(Sf[mf][nt][3] - mn1);
                ls0 += Sf[mf][nt][0] + Sf[mf][nt][1];
                ls1 += Sf[mf][nt][2] + Sf[mf][nt][3];
            }
            ls0 += __shfl_xor_sync(0xffffffffu, ls0, 1);
            ls0 += __shfl_xor_sync(0xffffffffu, ls0, 2);
            ls1 += __shfl_xor_sync(0xffffffffu, ls1, 1);
            ls1 += __shfl_xor_sync(0xffffffffu, ls1, 2);

            l[mf][0] = l[mf][0] * alp0 + ls0;  m[mf][0] = mn0;
            l[mf][1] = l[mf][1] * alp1 + ls1;  m[mf][1] = mn1;

            #pragma unroll
            for (int nt = 0; nt < 8; nt++) {
                O[mf][nt][0] *= alp0;  O[mf][nt][1] *= alp0;
                O[mf][nt][2] *= alp1;  O[mf][nt][3] *= alp1;
            }
        }

        // ---- O += P @ V ----
        const int src0 = (lane & ~3) + (t >> 1);
        const int src2 = src0 + 2;
        const bool odd = (t & 1);

        #pragma unroll
        for (int kc = 0; kc < 8; kc++) {
            uint32_t a[2][4];
            #pragma unroll
            for (int mf = 0; mf < 2; mf++) {
                float e0 = __shfl_sync(0xffffffffu, Sf[mf][kc][0], src0);
                float e1 = __shfl_sync(0xffffffffu, Sf[mf][kc][1], src0);
                float f0 = __shfl_sync(0xffffffffu, Sf[mf][kc][0], src2);
                float f1 = __shfl_sync(0xffffffffu, Sf[mf][kc][1], src2);
                float h0 = __shfl_sync(0xffffffffu, Sf[mf][kc][2], src0);
                float h1 = __shfl_sync(0xffffffffu, Sf[mf][kc][3], src0);
                float i0 = __shfl_sync(0xffffffffu, Sf[mf][kc][2], src2);
                float i1 = __shfl_sync(0xffffffffu, Sf[mf][kc][3], src2);
                a[mf][0] = f2tf(odd ? e1 : e0);
                a[mf][1] = f2tf(odd ? h1 : h0);
                a[mf][2] = f2tf(odd ? f1 : f0);
                a[mf][3] = f2tf(odd ? i1 : i0);
            }
            #pragma unroll
            for (int nt = 0; nt < 8; nt++) {
                int vi = (kc * 8 + t) * VP + nt * 8 + g;
                uint32_t bh0 = __float_as_uint(Vt[vi]);
                uint32_t bh1 = __float_as_uint(Vt[vi + 4 * VP]);
                #pragma unroll
                for (int mf = 0; mf < 2; mf++)
                    mma_tf32(O[mf][nt], a[mf][0], a[mf][1], a[mf][2], a[mf][3], bh0, bh1);
            }
        }
    }

    // ---- epilogue ----
    int b = bh >> 4;
    int h = bh & 15;
    #pragma unroll
    for (int mf = 0; mf < 2; mf++) {
        float inv0 = 1.f / l[mf][0];
        float inv1 = 1.f / l[mf][1];
        int srow = qt * 128 + wm + mf * 16 + g;
        size_t base0 = ((size_t)(b * S_ + srow) * H_ + h) * HD_;
        size_t base1 = base0 + (size_t)8 * H_ * HD_;
        #pragma unroll
        for (int nt = 0; nt < 8; nt++) {
            int col = nt * 8 + 2 * t;
            *(float2*)&out[base0 + col] =
                make_float2(O[mf][nt][0] * inv0, O[mf][nt][1] * inv0);
            *(float2*)&out[base1 + col] =
                make_float2(O[mf][nt][2] * inv1, O[mf][nt][3] * inv1);
        }
    }
}

extern "C" void kernel_launch(void* const* d_in, const int* in_sizes, int n_in,
                              void* d_out, int out_size)
{
    const float* hs = (const float*)d_in[0];
    const float* w  = (const float*)d_in[1];
    const float* qb = (const float*)d_in[2];
    const float* vb = (const float*)d_in[3];
    float* out = (float*)d_out;

    dim3 g1(N3_ / 128, M_ / 128);   // 24 x 32
    qkv_mma_kernel<<<g1, 256>>>(hs, w, qb, vb);

    cudaFuncSetAttribute(attn6_kernel,
                         cudaFuncAttributeMaxDynamicSharedMemorySize, ATTN_SMEM_BYTES);
    dim3 g2(S_ / 128, B_ * H_);     // 16 x 32
    attn6_kernel<<<g2, 128, ATTN_SMEM_BYTES>>>(out);
}

// round 11
// speedup vs baseline: 1.9295x; 1.2132x over previous
#include <cuda_runtime.h>
#include <math.h>
#include <stdint.h>

#define B_  2
#define S_  2048
#define D_  1024
#define H_  16
#define HD_ 64
#define M_  (B_ * S_)    // 4096
#define N3_ (3 * D_)     // 3072

// Scratch for Q/K/V in (b*H+h, s, e) layout.
__device__ float g_Q[(size_t)M_ * D_];      // raw fp32, pre-scaled by QSCALE
__device__ float g_K[(size_t)M_ * D_];      // tf32-rounded
__device__ float g_V[(size_t)M_ * D_];      // tf32-rounded

// ---------------------------------------------------------------------------
// TF32 helpers
// ---------------------------------------------------------------------------
__device__ __forceinline__ uint32_t f2tf(float x) {
    uint32_t r;
    asm("cvt.rna.tf32.f32 %0, %1;" : "=r"(r) : "f"(x));
    return r;
}
__device__ __forceinline__ float tf32r(float x) {
    uint32_t r;
    asm("cvt.rna.tf32.f32 %0, %1;" : "=r"(r) : "f"(x));
    return __uint_as_float(r);
}
__device__ __forceinline__ float ex2(float x) {
    float r;
    asm("ex2.approx.f32 %0, %1;" : "=f"(r) : "f"(x));
    return r;
}
__device__ __forceinline__ void mma_tf32(float c[4],
    uint32_t a0, uint32_t a1, uint32_t a2, uint32_t a3,
    uint32_t b0, uint32_t b1)
{
    asm volatile(
        "mma.sync.aligned.m16n8k8.row.col.f32.tf32.tf32.f32 "
        "{%0,%1,%2,%3}, {%4,%5,%6,%7}, {%8,%9}, {%0,%1,%2,%3};"
        : "+f"(c[0]), "+f"(c[1]), "+f"(c[2]), "+f"(c[3])
        : "r"(a0), "r"(a1), "r"(a2), "r"(a3), "r"(b0), "r"(b1));
}

// Q scale: 1/sqrt(64) * log2(e) -> scores in log2 domain, softmax via ex2
#define QSCALE 0.1803368801111204f

// ---------------------------------------------------------------------------
// Kernel 1: QKV projection, single-pass TF32 MMA (a_hi*w_hi).
// Round-4 skeleton (convert-in-kernel, reg prefetch, 2 syncs/slab); both
// A and W used tf32-rounded (W-lo drop measured +3.6e-4 in R10; A-lo drop
// expected symmetric).
// BM=128, BN=128, BK=16, 256 threads, warps 4(M)x2(N), warp tile 32x64.
// ---------------------------------------------------------------------------
#define GP_A 20
#define GP_W 136

__global__ __launch_bounds__(256, 2) void qkv_mma_kernel(
    const float* __restrict__ A, const float* __restrict__ W,
    const float* __restrict__ qbias, const float* __restrict__ vbias)
{
    __shared__ float Ahi[128 * GP_A];   // 10240 B
    __shared__ float Whi[16 * GP_W];    // 8704 B

    const int tid  = threadIdx.x;
    const int warp = tid >> 5;
    const int lane = tid & 31;
    const int g    = lane >> 2;
    const int t    = lane & 3;
    const int bm   = blockIdx.y * 128;
    const int bn   = blockIdx.x * 128;
    const int warpM = (warp >> 1) * 32;
    const int warpN = (warp & 1) * 64;

    float C[2][8][4];
    #pragma unroll
    for (int mf = 0; mf < 2; mf++)
        #pragma unroll
        for (int nf = 0; nf < 8; nf++)
            #pragma unroll
            for (int j = 0; j < 4; j++) C[mf][nf][j] = 0.f;

    int arow[2], acg[2], wkk[2], wnn[2];
    float4 pa[2], pw[2];
    #pragma unroll
    for (int i = 0; i < 2; i++) {
        int idx = tid + i * 256;
        arow[i] = idx >> 2;
        acg[i]  = (idx & 3) << 2;
        wkk[i]  = idx >> 5;
        wnn[i]  = (idx & 31) << 2;
        pa[i] = *(const float4*)(A + (size_t)(bm + arow[i]) * D_ + acg[i]);
        pw[i] = *(const float4*)(W + (size_t)wkk[i] * N3_ + bn + wnn[i]);
    }

    for (int k0 = 0; k0 < D_ / 16; k0++) {
        __syncthreads();

        #pragma unroll
        for (int i = 0; i < 2; i++) {
            float4 x = pa[i];
            *(float4*)&Ahi[arow[i] * GP_A + acg[i]] =
                make_float4(tf32r(x.x), tf32r(x.y), tf32r(x.z), tf32r(x.w));
            float4 y = pw[i];
            *(float4*)&Whi[wkk[i] * GP_W + wnn[i]] =
                make_float4(tf32r(y.x), tf32r(y.y), tf32r(y.z), tf32r(y.w));
        }
        __syncthreads();

        if (k0 < D_ / 16 - 1) {
            #pragma unroll
            for (int i = 0; i < 2; i++) {
                pa[i] = *(const float4*)(A + (size_t)(bm + arow[i]) * D_
                                           + (k0 + 1) * 16 + acg[i]);
                pw[i] = *(const float4*)(W + (size_t)((k0 + 1) * 16 + wkk[i]) * N3_
                                           + bn + wnn[i]);
            }
        }

        #pragma unroll
        for (int kc = 0; kc < 2; kc++) {
            uint32_t ah[2][4];
            #pragma unroll
            for (int mf = 0; mf < 2; mf++) {
                int r0 = (warpM + mf * 16 + g) * GP_A + kc * 8 + t;
                ah[mf][0] = __float_as_uint(Ahi[r0]);
                ah[mf][1] = __float_as_uint(Ahi[r0 + 8 * GP_A]);
                ah[mf][2] = __float_as_uint(Ahi[r0 + 4]);
                ah[mf][3] = __float_as_uint(Ahi[r0 + 8 * GP_A + 4]);
            }
            #pragma unroll
            for (int nf = 0; nf < 8; nf++) {
                int n  = warpN + nf * 8 + g;
                int kb = (kc * 8 + t) * GP_W + n;
                uint32_t bh0 = __float_as_uint(Whi[kb]);
                uint32_t bh1 = __float_as_uint(Whi[kb + 4 * GP_W]);
                #pragma unroll
                for (int mf = 0; mf < 2; mf++)
                    mma_tf32(C[mf][nf], ah[mf][0], ah[mf][1], ah[mf][2], ah[mf][3], bh0, bh1);
            }
        }
    }

    // Epilogue: scatter into (b*H+h, s, e); Q raw*QSCALE, K/V tf32-rounded.
    const int which = bn >> 10;
    #pragma unroll
    for (int mf = 0; mf < 2; mf++) {
        int mrow = bm + warpM + mf * 16 + g;
        int b = mrow >> 11;
        int s = mrow & (S_ - 1);
        #pragma unroll
        for (int nf = 0; nf < 8; nf++) {
            int ncol = bn + warpN + nf * 8 + 2 * t;
            int d = ncol & (D_ - 1);
            int h = d >> 6;
            int e = d & 63;
            size_t i0 = ((size_t)(b * H_ + h) * S_ + s) * HD_ + e;
            size_t i1 = i0 + 8 * HD_;
            float c0 = C[mf][nf][0], c1 = C[mf][nf][1];
            float c2 = C[mf][nf][2], c3 = C[mf][nf][3];
            if (which == 0) {
                float b0 = qbias[d], b1 = qbias[d + 1];
                *(float2*)&g_Q[i0] = make_float2((c0 + b0) * QSCALE, (c1 + b1) * QSCALE);
                *(float2*)&g_Q[i1] = make_float2((c2 + b0) * QSCALE, (c3 + b1) * QSCALE);
            } else if (which == 1) {
                *(float2*)&g_K[i0] = make_float2(tf32r(c0), tf32r(c1));
                *(float2*)&g_K[i1] = make_float2(tf32r(c2), tf32r(c3));
            } else {
                float b0 = vbias[d], b1 = vbias[d + 1];
                *(float2*)&g_V[i0] = make_float2(tf32r(c0 + b0), tf32r(c1 + b1));
                *(float2*)&g_V[i1] = make_float2(tf32r(c2 + b0), tf32r(c3 + b1));
            }
        }
    }
}

// ---------------------------------------------------------------------------
// Kernel 2: flash attention, TF32 MMA (attn6, UNCHANGED — matched prediction
// two rounds running; protect it).
// Block = 128 threads (4 warps), warp tile M=32, Br=128, Bc=64.
// QK = 2 MMAs (q_hi*k_hi + q_lo*k_hi); K/V arrive tf32-rounded from qkv,
// staging is pure copies. Softmax in log2 domain via ex2.
// smem: Qs [128][68] + Khi [64][68] + Vt [64][72] = 70656 B -> 2 blk/SM.
// ---------------------------------------------------------------------------
#define QP 68
#define KP 68
#define VP 72
#define SM_Q (128 * QP)
#define SM_K (64 * KP)
#define SM_V (64 * VP)
#define ATTN_SMEM_BYTES ((SM_Q + SM_K + SM_V) * (int)sizeof(float))   // 70656

__global__ __launch_bounds__(128, 2) void attn6_kernel(float* __restrict__ out)
{
    extern __shared__ float sm[];
    float* Qs  = sm;             // [128][QP] raw fp32 (pre-scaled)
    float* Khi = Qs + SM_Q;      // [64][KP] tf32-rounded fp32
    float* Vt  = Khi + SM_K;     // [64][VP] tf32-rounded fp32

    const int tid  = threadIdx.x;
    const int warp = tid >> 5;
    const int lane = tid & 31;
    const int g    = lane >> 2;
    const int t    = lane & 3;
    const int wm   = warp * 32;
    const int bh   = blockIdx.y;
    const int qt   = blockIdx.x;

    const float* Qg = g_Q + ((size_t)bh * S_ + qt * 128) * HD_;
    const float* Kg = g_K + (size_t)bh * S_ * HD_;
    const float* Vg = g_V + (size_t)bh * S_ * HD_;

    #pragma unroll
    for (int i = 0; i < 16; i++) {
        int idx = tid + i * 128;
        int row = idx >> 4;
        int col = (idx & 15) << 2;
        *(float4*)&Qs[row * QP + col] = *(const float4*)(Qg + row * HD_ + col);
    }

    float m[2][2], l[2][2];
    #pragma unroll
    for (int mf = 0; mf < 2; mf++) {
        m[mf][0] = -INFINITY; m[mf][1] = -INFINITY;
        l[mf][0] = 0.f;       l[mf][1] = 0.f;
    }
    float O[2][8][4];
    #pragma unroll
    for (int mf = 0; mf < 2; mf++)
        #pragma unroll
        for (int nt = 0; nt < 8; nt++)
            #pragma unroll
            for (int j = 0; j < 4; j++) O[mf][nt][j] = 0.f;

    for (int kt = 0; kt < S_ / 64; kt++) {
        __syncthreads();

        // ---- stage K and V: pure float4 copies (data already tf32) ----
        const float* Kt = Kg + (size_t)kt * 64 * HD_;
        const float* Vp = Vg + (size_t)kt * 64 * HD_;
        #pragma unroll
        for (int i = 0; i < 8; i++) {
            int idx = tid + i * 128;
            int row = idx >> 4;
            int col = (idx & 15) << 2;
            *(float4*)&Khi[row * KP + col] = *(const float4*)(Kt + row * HD_ + col);
            *(float4*)&Vt[row * VP + col]  = *(const float4*)(Vp + row * HD_ + col);
        }
        __syncthreads();

        // ---- scores (log2 domain): 2 MMAs (hi*hi + lo*hi) ----
        float Sf[2][8][4];
        #pragma unroll
        for (int mf = 0; mf < 2; mf++)
            #pragma unroll
            for (int nt = 0; nt < 8; nt++)
                #pragma unroll
                for (int j = 0; j < 4; j++) Sf[mf][nt][j] = 0.f;

        #pragma unroll
        for (int kc = 0; kc < 8; kc++) {
            uint32_t ah[2][4], al[2][4];
            #pragma unroll
            for (int mf = 0; mf < 2; mf++) {
                int qi = (wm + mf * 16 + g) * QP + kc * 8 + t;
                float a0f = Qs[qi];
                float a1f = Qs[qi + 8 * QP];
                float a2f = Qs[qi + 4];
                float a3f = Qs[qi + 8 * QP + 4];
                ah[mf][0] = f2tf(a0f); ah[mf][1] = f2tf(a1f);
                ah[mf][2] = f2tf(a2f); ah[mf][3] = f2tf(a3f);
                al[mf][0] = f2tf(a0f - __uint_as_float(ah[mf][0]));
                al[mf][1] = f2tf(a1f - __uint_as_float(ah[mf][1]));
                al[mf][2] = f2tf(a2f - __uint_as_float(ah[mf][2]));
                al[mf][3] = f2tf(a3f - __uint_as_float(ah[mf][3]));
            }
            #pragma unroll
            for (int nt = 0; nt < 8; nt++) {
                int kb = (nt * 8 + g) * KP + kc * 8 + t;
                uint32_t bh0 = __float_as_uint(Khi[kb]);
                uint32_t bh1 = __float_as_uint(Khi[kb + 4]);
                #pragma unroll
                for (int mf = 0; mf < 2; mf++) {
                    mma_tf32(Sf[mf][nt], ah[mf][0], ah[mf][1], ah[mf][2], ah[mf][3], bh0, bh1);
                    mma_tf32(Sf[mf][nt], al[mf][0], al[mf][1], al[mf][2], al[mf][3], bh0, bh1);
                }
            }
        }

        // ---- online softmax (base-2) ----
        #pragma unroll
        for (int mf = 0; mf < 2; mf++) {
            float mx0 = -INFINITY, mx1 = -INFINITY;
            #pragma unroll
            for (int nt = 0; nt < 8; nt++) {
                mx0 = fmaxf(mx0, fmaxf(Sf[mf][nt][0], Sf[mf][nt][1]));
                mx1 = fmaxf(mx1, fmaxf(Sf[mf][nt][2], Sf[mf][nt][3]));
            }
            mx0 = fmaxf(mx0, __shfl_xor_sync(0xffffffffu, mx0, 1));
            mx0 = fmaxf(mx0, __shfl_xor_sync(0xffffffffu, mx0, 2));
            mx1 = fmaxf(mx1, __shfl_xor_sync(0xffffffffu, mx1, 1));
            mx1 = fmaxf(mx1, __shfl_xor_sync(0xffffffffu, mx1, 2));

            float mn0 = fmaxf(m[mf][0], mx0);
            float mn1 = fmaxf(m[mf][1], mx1);
            float alp0 = ex2(m[mf][0] - mn0);
            float alp1 = ex2(m[mf][1] - mn1);

            float ls0 = 0.f, ls1 = 0.f;
            #pragma unroll
            for (int nt = 0; nt < 8; nt++) {
                Sf[mf][nt][0] = ex2(Sf[mf][nt][0] - mn0);
                Sf[mf][nt][1] = ex2(Sf[mf][nt][1] - mn0);
                Sf[mf][nt][2] = ex2(Sf[mf][nt][2] - mn1);
                Sf[mf][nt][3] = ex2(Sf[mf][nt][3] - mn1);
                ls0 += Sf[mf][nt][0] + Sf[mf][nt][1];
                ls1 += Sf[mf][nt][2] + Sf[mf][nt][3];
            }
            ls0 += __shfl_xor_sync(0xffffffffu, ls0, 1);
            ls0 += __shfl_xor_sync(0xffffffffu, ls0, 2);
            ls1 += __shfl_xor_sync(0xffffffffu, ls1, 1);
            ls1 += __shfl_xor_sync(0xffffffffu, ls1, 2);

            l[mf][0] = l[mf][0] * alp0 + ls0;  m[mf][0] = mn0;
            l[mf][1] = l[mf][1] * alp1 + ls1;  m[mf][1] = mn1;

            #pragma unroll
            for (int nt = 0; nt < 8; nt++) {
                O[mf][nt][0] *= alp0;  O[mf][nt][1] *= alp0;
                O[mf][nt][2] *= alp1;  O[mf][nt][3] *= alp1;
            }
        }

        // ---- O += P @ V ----
        const int src0 = (lane & ~3) + (t >> 1);
        const int src2 = src0 + 2;
        const bool odd = (t & 1);

        #pragma unroll
        for (int kc = 0; kc < 8; kc++) {
            uint32_t a[2][4];
            #pragma unroll
            for (int mf = 0; mf < 2; mf++) {
                float e0 = __shfl_sync(0xffffffffu, Sf[mf][kc][0], src0);
                float e1 = __shfl_sync(0xffffffffu, Sf[mf][kc][1], src0);
                float f0 = __shfl_sync(0xffffffffu, Sf[mf][kc][0], src2);
                float f1 = __shfl_sync(0xffffffffu, Sf[mf][kc][1], src2);
                float h0 = __shfl_sync(0xffffffffu, Sf[mf][kc][2], src0);
                float h1 = __shfl_sync(0xffffffffu, Sf[mf][kc][3], src0);
                float i0 = __shfl_sync(0xffffffffu, Sf[mf][kc][2], src2);
                float i1 = __shfl_sync(0xffffffffu, Sf[mf][kc][3], src2);
                a[mf][0] = f2tf(odd ? e1 : e0);
                a[mf][1] = f2tf(odd ? h1 : h0);
                a[mf][2] = f2tf(odd ? f1 : f0);
                a[mf][3] = f2tf(odd ? i1 : i0);
            }
            #pragma unroll
            for (int nt = 0; nt < 8; nt++) {
                int vi = (kc * 8 + t) * VP + nt * 8 + g;
                uint32_t bh0 = __float_as_uint(Vt[vi]);
                uint32_t bh1 = __float_as_uint(Vt[vi + 4 * VP]);
                #pragma unroll
                for (int mf = 0; mf < 2; mf++)
                    mma_tf32(O[mf][nt], a[mf][0], a[mf][1], a[mf][2], a[mf][3], bh0, bh1);
            }
        }
    }

    // ---- epilogue ----
    int b = bh >> 4;
    int h = bh & 15;
    #pragma unroll
    for (int mf = 0; mf < 2; mf++) {
        float inv0 = 1.f / l[mf][0];
        float inv1 = 1.f / l[mf][1];
        int srow = qt * 128 + wm + mf * 16 + g;
        size_t base0 = ((size_t)(b * S_ + srow) * H_ + h) * HD_;
        size_t base1 = base0 + (size_t)8 * H_ * HD_;
        #pragma unroll
        for (int nt = 0; nt < 8; nt++) {
            int col = nt * 8 + 2 * t;
            *(float2*)&out[base0 + col] =
                make_float2(O[mf][nt][0] * inv0, O[mf][nt][1] * inv0);
            *(float2*)&out[base1 + col] =
                make_float2(O[mf][nt][2] * inv1, O[mf][nt][3] * inv1);
        }
    }
}

extern "C" void kernel_launch(void* const* d_in, const int* in_sizes, int n_in,
                              void* d_out, int out_size)
{
    const float* hs = (const float*)d_in[0];
    const float* w  = (const float*)d_in[1];
    const float* qb = (const float*)d_in[2];
    const float* vb = (const float*)d_in[3];
    float* out = (float*)d_out;

    dim3 g1(N3_ / 128, M_ / 128);   // 24 x 32
    qkv_mma_kernel<<<g1, 256>>>(hs, w, qb, vb);

    cudaFuncSetAttribute(attn6_kernel,
                         cudaFuncAttributeMaxDynamicSharedMemorySize, ATTN_SMEM_BYTES);
    dim3 g2(S_ / 128, B_ * H_);     // 16 x 32
    attn6_kernel<<<g2, 128, ATTN_SMEM_BYTES>>>(out);
}

// round 12
// speedup vs baseline: 2.2888x; 1.1862x over previous
#include <cuda_runtime.h>
#include <math.h>
#include <stdint.h>

#define B_  2
#define S_  2048
#define D_  1024
#define H_  16
#define HD_ 64
#define M_  (B_ * S_)    // 4096
#define N3_ (3 * D_)     // 3072

// Scratch for Q/K/V in (b*H+h, s, e) layout. All tf32-rounded now.
__device__ float g_Q[(size_t)M_ * D_];      // tf32-rounded, pre-scaled by QSCALE
__device__ float g_K[(size_t)M_ * D_];      // tf32-rounded
__device__ float g_V[(size_t)M_ * D_];      // tf32-rounded

// ---------------------------------------------------------------------------
// TF32 helpers
// ---------------------------------------------------------------------------
__device__ __forceinline__ uint32_t f2tf(float x) {
    uint32_t r;
    asm("cvt.rna.tf32.f32 %0, %1;" : "=r"(r) : "f"(x));
    return r;
}
__device__ __forceinline__ float tf32r(float x) {
    uint32_t r;
    asm("cvt.rna.tf32.f32 %0, %1;" : "=r"(r) : "f"(x));
    return __uint_as_float(r);
}
__device__ __forceinline__ float ex2(float x) {
    float r;
    asm("ex2.approx.f32 %0, %1;" : "=f"(r) : "f"(x));
    return r;
}
__device__ __forceinline__ void mma_tf32(float c[4],
    uint32_t a0, uint32_t a1, uint32_t a2, uint32_t a3,
    uint32_t b0, uint32_t b1)
{
    asm volatile(
        "mma.sync.aligned.m16n8k8.row.col.f32.tf32.tf32.f32 "
        "{%0,%1,%2,%3}, {%4,%5,%6,%7}, {%8,%9}, {%0,%1,%2,%3};"
        : "+f"(c[0]), "+f"(c[1]), "+f"(c[2]), "+f"(c[3])
        : "r"(a0), "r"(a1), "r"(a2), "r"(a3), "r"(b0), "r"(b1));
}

// Q scale: 1/sqrt(64) * log2(e) -> scores in log2 domain, softmax via ex2
#define QSCALE 0.1803368801111204f

// ---------------------------------------------------------------------------
// Kernel 1: QKV projection, single-pass TF32 MMA (unchanged from R11 except
// Q is now stored tf32-rounded for attn's single-MMA QK).
// BM=128, BN=128, BK=16, 256 threads, warps 4(M)x2(N), warp tile 32x64.
// ---------------------------------------------------------------------------
#define GP_A 20
#define GP_W 136

__global__ __launch_bounds__(256, 2) void qkv_mma_kernel(
    const float* __restrict__ A, const float* __restrict__ W,
    const float* __restrict__ qbias, const float* __restrict__ vbias)
{
    __shared__ float Ahi[128 * GP_A];   // 10240 B
    __shared__ float Whi[16 * GP_W];    // 8704 B

    const int tid  = threadIdx.x;
    const int warp = tid >> 5;
    const int lane = tid & 31;
    const int g    = lane >> 2;
    const int t    = lane & 3;
    const int bm   = blockIdx.y * 128;
    const int bn   = blockIdx.x * 128;
    const int warpM = (warp >> 1) * 32;
    const int warpN = (warp & 1) * 64;

    float C[2][8][4];
    #pragma unroll
    for (int mf = 0; mf < 2; mf++)
        #pragma unroll
        for (int nf = 0; nf < 8; nf++)
            #pragma unroll
            for (int j = 0; j < 4; j++) C[mf][nf][j] = 0.f;

    int arow[2], acg[2], wkk[2], wnn[2];
    float4 pa[2], pw[2];
    #pragma unroll
    for (int i = 0; i < 2; i++) {
        int idx = tid + i * 256;
        arow[i] = idx >> 2;
        acg[i]  = (idx & 3) << 2;
        wkk[i]  = idx >> 5;
        wnn[i]  = (idx & 31) << 2;
        pa[i] = *(const float4*)(A + (size_t)(bm + arow[i]) * D_ + acg[i]);
        pw[i] = *(const float4*)(W + (size_t)wkk[i] * N3_ + bn + wnn[i]);
    }

    for (int k0 = 0; k0 < D_ / 16; k0++) {
        __syncthreads();

        #pragma unroll
        for (int i = 0; i < 2; i++) {
            float4 x = pa[i];
            *(float4*)&Ahi[arow[i] * GP_A + acg[i]] =
                make_float4(tf32r(x.x), tf32r(x.y), tf32r(x.z), tf32r(x.w));
            float4 y = pw[i];
            *(float4*)&Whi[wkk[i] * GP_W + wnn[i]] =
                make_float4(tf32r(y.x), tf32r(y.y), tf32r(y.z), tf32r(y.w));
        }
        __syncthreads();

        if (k0 < D_ / 16 - 1) {
            #pragma unroll
            for (int i = 0; i < 2; i++) {
                pa[i] = *(const float4*)(A + (size_t)(bm + arow[i]) * D_
                                           + (k0 + 1) * 16 + acg[i]);
                pw[i] = *(const float4*)(W + (size_t)((k0 + 1) * 16 + wkk[i]) * N3_
                                           + bn + wnn[i]);
            }
        }

        #pragma unroll
        for (int kc = 0; kc < 2; kc++) {
            uint32_t ah[2][4];
            #pragma unroll
            for (int mf = 0; mf < 2; mf++) {
                int r0 = (warpM + mf * 16 + g) * GP_A + kc * 8 + t;
                ah[mf][0] = __float_as_uint(Ahi[r0]);
                ah[mf][1] = __float_as_uint(Ahi[r0 + 8 * GP_A]);
                ah[mf][2] = __float_as_uint(Ahi[r0 + 4]);
                ah[mf][3] = __float_as_uint(Ahi[r0 + 8 * GP_A + 4]);
            }
            #pragma unroll
            for (int nf = 0; nf < 8; nf++) {
                int n  = warpN + nf * 8 + g;
                int kb = (kc * 8 + t) * GP_W + n;
                uint32_t bh0 = __float_as_uint(Whi[kb]);
                uint32_t bh1 = __float_as_uint(Whi[kb + 4 * GP_W]);
                #pragma unroll
                for (int mf = 0; mf < 2; mf++)
                    mma_tf32(C[mf][nf], ah[mf][0], ah[mf][1], ah[mf][2], ah[mf][3], bh0, bh1);
            }
        }
    }

    // Epilogue: scatter into (b*H+h, s, e); all three tf32-rounded.
    const int which = bn >> 10;
    #pragma unroll
    for (int mf = 0; mf < 2; mf++) {
        int mrow = bm + warpM + mf * 16 + g;
        int b = mrow >> 11;
        int s = mrow & (S_ - 1);
        #pragma unroll
        for (int nf = 0; nf < 8; nf++) {
            int ncol = bn + warpN + nf * 8 + 2 * t;
            int d = ncol & (D_ - 1);
            int h = d >> 6;
            int e = d & 63;
            size_t i0 = ((size_t)(b * H_ + h) * S_ + s) * HD_ + e;
            size_t i1 = i0 + 8 * HD_;
            float c0 = C[mf][nf][0], c1 = C[mf][nf][1];
            float c2 = C[mf][nf][2], c3 = C[mf][nf][3];
            if (which == 0) {
                float b0 = qbias[d], b1 = qbias[d + 1];
                *(float2*)&g_Q[i0] = make_float2(tf32r((c0 + b0) * QSCALE),
                                                 tf32r((c1 + b1) * QSCALE));
                *(float2*)&g_Q[i1] = make_float2(tf32r((c2 + b0) * QSCALE),
                                                 tf32r((c3 + b1) * QSCALE));
            } else if (which == 1) {
                *(float2*)&g_K[i0] = make_float2(tf32r(c0), tf32r(c1));
                *(float2*)&g_K[i1] = make_float2(tf32r(c2), tf32r(c3));
            } else {
                float b0 = vbias[d], b1 = vbias[d + 1];
                *(float2*)&g_V[i0] = make_float2(tf32r(c0 + b0), tf32r(c1 + b1));
                *(float2*)&g_V[i1] = make_float2(tf32r(c2 + b0), tf32r(c3 + b1));
            }
        }
    }
}

// ---------------------------------------------------------------------------
// Kernel 2: flash attention, single-MMA QK (q_hi*k_hi) — Q arrives
// tf32-rounded, so QK fragment loads are pure LDS (no cvt in the loop).
// Block = 128 threads (4 warps), warp tile M=32, Br=128, Bc=64.
// PV = 1 MMA (P tf32 via shuffles, V tf32-rounded). Softmax base-2 via ex2.
// smem: Qs [128][68] + Khi [64][68] + Vt [64][72] = 70656 B -> 2 blk/SM.
// ---------------------------------------------------------------------------
#define QP 68
#define KP 68
#define VP 72
#define SM_Q (128 * QP)
#define SM_K (64 * KP)
#define SM_V (64 * VP)
#define ATTN_SMEM_BYTES ((SM_Q + SM_K + SM_V) * (int)sizeof(float))   // 70656

__global__ __launch_bounds__(128, 2) void attn7_kernel(float* __restrict__ out)
{
    extern __shared__ float sm[];
    float* Qs  = sm;             // [128][QP] tf32-rounded, pre-scaled
    float* Khi = Qs + SM_Q;      // [64][KP] tf32-rounded
    float* Vt  = Khi + SM_K;     // [64][VP] tf32-rounded

    const int tid  = threadIdx.x;
    const int warp = tid >> 5;
    const int lane = tid & 31;
    const int g    = lane >> 2;
    const int t    = lane & 3;
    const int wm   = warp * 32;
    const int bh   = blockIdx.y;
    const int qt   = blockIdx.x;

    const float* Qg = g_Q + ((size_t)bh * S_ + qt * 128) * HD_;
    const float* Kg = g_K + (size_t)bh * S_ * HD_;
    const float* Vg = g_V + (size_t)bh * S_ * HD_;

    #pragma unroll
    for (int i = 0; i < 16; i++) {
        int idx = tid + i * 128;
        int row = idx >> 4;
        int col = (idx & 15) << 2;
        *(float4*)&Qs[row * QP + col] = *(const float4*)(Qg + row * HD_ + col);
    }

    float m[2][2], l[2][2];
    #pragma unroll
    for (int mf = 0; mf < 2; mf++) {
        m[mf][0] = -INFINITY; m[mf][1] = -INFINITY;
        l[mf][0] = 0.f;       l[mf][1] = 0.f;
    }
    float O[2][8][4];
    #pragma unroll
    for (int mf = 0; mf < 2; mf++)
        #pragma unroll
        for (int nt = 0; nt < 8; nt++)
            #pragma unroll
            for (int j = 0; j < 4; j++) O[mf][nt][j] = 0.f;

    for (int kt = 0; kt < S_ / 64; kt++) {
        __syncthreads();

        // ---- stage K and V: pure float4 copies (data already tf32) ----
        const float* Kt = Kg + (size_t)kt * 64 * HD_;
        const float* Vp = Vg + (size_t)kt * 64 * HD_;
        #pragma unroll
        for (int i = 0; i < 8; i++) {
            int idx = tid + i * 128;
            int row = idx >> 4;
            int col = (idx & 15) << 2;
            *(float4*)&Khi[row * KP + col] = *(const float4*)(Kt + row * HD_ + col);
            *(float4*)&Vt[row * VP + col]  = *(const float4*)(Vp + row * HD_ + col);
        }
        __syncthreads();

        // ---- scores (log2 domain): 1 MMA, fragments are pure LDS ----
        float Sf[2][8][4];
        #pragma unroll
        for (int mf = 0; mf < 2; mf++)
            #pragma unroll
            for (int nt = 0; nt < 8; nt++)
                #pragma unroll
                for (int j = 0; j < 4; j++) Sf[mf][nt][j] = 0.f;

        #pragma unroll
        for (int kc = 0; kc < 8; kc++) {
            uint32_t ah[2][4];
            #pragma unroll
            for (int mf = 0; mf < 2; mf++) {
                int qi = (wm + mf * 16 + g) * QP + kc * 8 + t;
                ah[mf][0] = __float_as_uint(Qs[qi]);
                ah[mf][1] = __float_as_uint(Qs[qi + 8 * QP]);
                ah[mf][2] = __float_as_uint(Qs[qi + 4]);
                ah[mf][3] = __float_as_uint(Qs[qi + 8 * QP + 4]);
            }
            #pragma unroll
            for (int nt = 0; nt < 8; nt++) {
                int kb = (nt * 8 + g) * KP + kc * 8 + t;
                uint32_t bh0 = __float_as_uint(Khi[kb]);
                uint32_t bh1 = __float_as_uint(Khi[kb + 4]);
                #pragma unroll
                for (int mf = 0; mf < 2; mf++)
                    mma_tf32(Sf[mf][nt], ah[mf][0], ah[mf][1], ah[mf][2], ah[mf][3], bh0, bh1);
            }
        }

        // ---- online softmax (base-2) ----
        #pragma unroll
        for (int mf = 0; mf < 2; mf++) {
            float mx0 = -INFINITY, mx1 = -INFINITY;
            #pragma unroll
            for (int nt = 0; nt < 8; nt++) {
                mx0 = fmaxf(mx0, fmaxf(Sf[mf][nt][0], Sf[mf][nt][1]));
                mx1 = fmaxf(mx1, fmaxf(Sf[mf][nt][2], Sf[mf][nt][3]));
            }
            mx0 = fmaxf(mx0, __shfl_xor_sync(0xffffffffu, mx0, 1));
            mx0 = fmaxf(mx0, __shfl_xor_sync(0xffffffffu, mx0, 2));
            mx1 = fmaxf(mx1, __shfl_xor_sync(0xffffffffu, mx1, 1));
            mx1 = fmaxf(mx1, __shfl_xor_sync(0xffffffffu, mx1, 2));

            float mn0 = fmaxf(m[mf][0], mx0);
            float mn1 = fmaxf(m[mf][1], mx1);
            float alp0 = ex2(m[mf][0] - mn0);
            float alp1 = ex2(m[mf][1] - mn1);

            float ls0 = 0.f, ls1 = 0.f;
            #pragma unroll
            for (int nt = 0; nt < 8; nt++) {
                Sf[mf][nt][0] = ex2(Sf[mf][nt][0] - mn0);
                Sf[mf][nt][1] = ex2(Sf[mf][nt][1] - mn0);
                Sf[mf][nt][2] = ex2(Sf[mf][nt][2] - mn1);
                Sf[mf][nt][3] = ex2(Sf[mf][nt][3] - mn1);
                ls0 += Sf[mf][nt][0] + Sf[mf][nt][1];
                ls1 += Sf[mf][nt][2] + Sf[mf][nt][3];
            }
            ls0 += __shfl_xor_sync(0xffffffffu, ls0, 1);
            ls0 += __shfl_xor_sync(0xffffffffu, ls0, 2);
            ls1 += __shfl_xor_sync(0xffffffffu, ls1, 1);
            ls1 += __shfl_xor_sync(0xffffffffu, ls1, 2);

            l[mf][0] = l[mf][0] * alp0 + ls0;  m[mf][0] = mn0;
            l[mf][1] = l[mf][1] * alp1 + ls1;  m[mf][1] = mn1;

            #pragma unroll
            for (int nt = 0; nt < 8; nt++) {
                O[mf][nt][0] *= alp0;  O[mf][nt][1] *= alp0;
                O[mf][nt][2] *= alp1;  O[mf][nt][3] *= alp1;
            }
        }

        // ---- O += P @ V ----
        const int src0 = (lane & ~3) + (t >> 1);
        const int src2 = src0 + 2;
        const bool odd = (t & 1);

        #pragma unroll
        for (int kc = 0; kc < 8; kc++) {
            uint32_t a[2][4];
            #pragma unroll
            for (int mf = 0; mf < 2; mf++) {
                float e0 = __shfl_sync(0xffffffffu, Sf[mf][kc][0], src0);
                float e1 = __shfl_sync(0xffffffffu, Sf[mf][kc][1], src0);
                float f0 = __shfl_sync(0xffffffffu, Sf[mf][kc][0], src2);
                float f1 = __shfl_sync(0xffffffffu, Sf[mf][kc][1], src2);
                float h0 = __shfl_sync(0xffffffffu, Sf[mf][kc][2], src0);
                float h1 = __shfl_sync(0xffffffffu, Sf[mf][kc][3], src0);
                float i0 = __shfl_sync(0xffffffffu, Sf[mf][kc][2], src2);
                float i1 = __shfl_sync(0xffffffffu, Sf[mf][kc][3], src2);
                a[mf][0] = f2tf(odd ? e1 : e0);
                a[mf][1] = f2tf(odd ? h1 : h0);
                a[mf][2] = f2tf(odd ? f1 : f0);
                a[mf][3] = f2tf(odd ? i1 : i0);
            }
            #pragma unroll
            for (int nt = 0; nt < 8; nt++) {
                int vi = (kc * 8 + t) * VP + nt * 8 + g;
                uint32_t bh0 = __float_as_uint(Vt[vi]);
                uint32_t bh1 = __float_as_uint(Vt[vi + 4 * VP]);
                #pragma unroll
                for (int mf = 0; mf < 2; mf++)
                    mma_tf32(O[mf][nt], a[mf][0], a[mf][1], a[mf][2], a[mf][3], bh0, bh1);
            }
        }
    }

    // ---- epilogue ----
    int b = bh >> 4;
    int h = bh & 15;
    #pragma unroll
    for (int mf = 0; mf < 2; mf++) {
        float inv0 = 1.f / l[mf][0];
        float inv1 = 1.f / l[mf][1];
        int srow = qt * 128 + wm + mf * 16 + g;
        size_t base0 = ((size_t)(b * S_ + srow) * H_ + h) * HD_;
        size_t base1 = base0 + (size_t)8 * H_ * HD_;
        #pragma unroll
        for (int nt = 0; nt < 8; nt++) {
            int col = nt * 8 + 2 * t;
            *(float2*)&out[base0 + col] =
                make_float2(O[mf][nt][0] * inv0, O[mf][nt][1] * inv0);
            *(float2*)&out[base1 + col] =
                make_float2(O[mf][nt][2] * inv1, O[mf][nt][3] * inv1);
        }
    }
}

extern "C" void kernel_launch(void* const* d_in, const int* in_sizes, int n_in,
                              void* d_out, int out_size)
{
    const float* hs = (const float*)d_in[0];
    const float* w  = (const float*)d_in[1];
    const float* qb = (const float*)d_in[2];
    const float* vb = (const float*)d_in[3];
    float* out = (float*)d_out;

    dim3 g1(N3_ / 128, M_ / 128);   // 24 x 32
    qkv_mma_kernel<<<g1, 256>>>(hs, w, qb, vb);

    cudaFuncSetAttribute(attn7_kernel,
                         cudaFuncAttributeMaxDynamicSharedMemorySize, ATTN_SMEM_BYTES);
    dim3 g2(S_ / 128, B_ * H_);     // 16 x 32
    attn7_kernel<<<g2, 128, ATTN_SMEM_BYTES>>>(out);
}